// round 6
// baseline (speedup 1.0000x reference)
#include <cuda_runtime.h>
#include <cstdint>

#define DIM 1024
#define HEADS 16
#define DH 64
#define SEQ 2048
#define NB 2
#define ROWS (NB * SEQ)        // 4096
#define SCALE 0.125f
#define LOG2E 1.4426950408889634f
#define LNEPS 1e-5f

// ---------------- scratch ----------------
__device__ float g_mu[ROWS];
__device__ float g_rs[ROWS];
__device__ float g_q[ROWS * DIM];      // tf32 bits, pre-scaled by SCALE*LOG2E
__device__ float g_k[ROWS * DIM];      // tf32 bits
__device__ float g_v[ROWS * DIM];      // tf32 bits
__device__ float g_attn[ROWS * DIM];   // fp32, heads re-merged [4096,1024]
__device__ float g_wcomb[DIM * DIM];   // wo @ w_out (fp32)

// ---------------- helpers ----------------
__device__ __forceinline__ unsigned f2tf(float x) {
    unsigned u;
    asm("cvt.rna.tf32.f32 %0, %1;" : "=r"(u) : "f"(x));
    return u;
}
__device__ __forceinline__ void mma8(float* c, const unsigned* a, unsigned b0, unsigned b1) {
    asm volatile(
        "mma.sync.aligned.m16n8k8.row.col.f32.tf32.tf32.f32 "
        "{%0,%1,%2,%3}, {%4,%5,%6,%7}, {%8,%9}, {%0,%1,%2,%3};\n"
        : "+f"(c[0]), "+f"(c[1]), "+f"(c[2]), "+f"(c[3])
        : "r"(a[0]), "r"(a[1]), "r"(a[2]), "r"(a[3]), "r"(b0), "r"(b1));
}
__device__ __forceinline__ void cpa16(unsigned dst, const void* src) {
    asm volatile("cp.async.cg.shared.global [%0], [%1], 16;\n" :: "r"(dst), "l"(src));
}

// ---------------- LayerNorm stats only ----------------
__global__ void __launch_bounds__(256) ln_stats(const float* __restrict__ x)
{
    int row = blockIdx.x;
    int t = threadIdx.x;
    const float4* xr = (const float4*)(x + (size_t)row * DIM);
    float4 v = xr[t];
    float s = v.x + v.y + v.z + v.w;
    float ss = v.x * v.x + v.y * v.y + v.z * v.z + v.w * v.w;
    #pragma unroll
    for (int o = 16; o > 0; o >>= 1) {
        s  += __shfl_xor_sync(0xffffffffu, s, o);
        ss += __shfl_xor_sync(0xffffffffu, ss, o);
    }
    __shared__ float sb[8], ssb[8];
    int w = t >> 5, ln = t & 31;
    if (ln == 0) { sb[w] = s; ssb[w] = ss; }
    __syncthreads();
    if (t == 0) {
        float tot = 0.f, tot2 = 0.f;
        #pragma unroll
        for (int i = 0; i < 8; i++) { tot += sb[i]; tot2 += ssb[i]; }
        float mu = tot * (1.f / DIM);
        float var = tot2 * (1.f / DIM) - mu * mu;
        g_mu[row] = mu;
        g_rs[row] = rsqrtf(var + LNEPS);
    }
}

// ---------------- tf32 tensor-core GEMM cores ----------------
#define BM 128
#define BN 128
#define BK 32
#define APAD 36     // bank = 4*row + col -> frag loads conflict-free
#define BPAD 136    // bank = 8*row + col -> frag loads conflict-free

// Plain core: C tile = A @ B
__device__ __forceinline__ void gemm_tc_core(const float* __restrict__ A,
                                             const float* __restrict__ B,
                                             int K, int N, float acc[2][8][4])
{
    __shared__ unsigned As[BM][APAD];
    __shared__ unsigned Bs[BK][BPAD];
    const int t = threadIdx.x;
    const int wid = t >> 5, lane = t & 31;
    const int g = lane >> 2, q4 = lane & 3;
    const int wm = wid & 3, wn = wid >> 2;
    const int row0 = blockIdx.y * BM, col0 = blockIdx.x * BN;

    const int arow = t >> 3, acol = (t & 7) * 4;
    const int brow = t >> 5, bcol = (t & 31) * 4;

    const float* Ap = A + (size_t)(row0 + arow) * K + acol;
    const float* Bp = B + (size_t)brow * N + col0 + bcol;

    float4 la[4], lb[4];
    #pragma unroll
    for (int i = 0; i < 4; i++) la[i] = *(const float4*)(Ap + (size_t)(32 * i) * K);
    #pragma unroll
    for (int i = 0; i < 4; i++) lb[i] = *(const float4*)(Bp + (size_t)(8 * i) * N);

    for (int k0 = 0; k0 < K; k0 += BK) {
        __syncthreads();
        #pragma unroll
        for (int i = 0; i < 4; i++) {
            uint4 vv;
            vv.x = f2tf(la[i].x); vv.y = f2tf(la[i].y);
            vv.z = f2tf(la[i].z); vv.w = f2tf(la[i].w);
            *(uint4*)&As[arow + 32 * i][acol] = vv;
        }
        #pragma unroll
        for (int i = 0; i < 4; i++) {
            uint4 vv;
            vv.x = f2tf(lb[i].x); vv.y = f2tf(lb[i].y);
            vv.z = f2tf(lb[i].z); vv.w = f2tf(lb[i].w);
            *(uint4*)&Bs[brow + 8 * i][bcol] = vv;
        }
        __syncthreads();
        if (k0 + BK < K) {
            #pragma unroll
            for (int i = 0; i < 4; i++)
                la[i] = *(const float4*)(Ap + k0 + BK + (size_t)(32 * i) * K);
            #pragma unroll
            for (int i = 0; i < 4; i++)
                lb[i] = *(const float4*)(Bp + (size_t)(k0 + BK + 8 * i) * N);
        }
        #pragma unroll
        for (int kk = 0; kk < 4; kk++) {
            unsigned af[2][4];
            #pragma unroll
            for (int mt = 0; mt < 2; mt++) {
                int r = wm * 32 + mt * 16;
                af[mt][0] = As[r + g][kk * 8 + q4];
                af[mt][1] = As[r + g + 8][kk * 8 + q4];
                af[mt][2] = As[r + g][kk * 8 + q4 + 4];
                af[mt][3] = As[r + g + 8][kk * 8 + q4 + 4];
            }
            #pragma unroll
            for (int nt = 0; nt < 8; nt++) {
                int cb = wn * 64 + nt * 8 + g;
                unsigned b0 = Bs[kk * 8 + q4][cb];
                unsigned b1 = Bs[kk * 8 + q4 + 4][cb];
                mma8(acc[0][nt], af[0], b0, b1);
                mma8(acc[1][nt], af[1], b0, b1);
            }
        }
    }
}

// LN-fused core: A = layernorm(x) applied on the fly during the A-panel load.
__device__ __forceinline__ void gemm_tc_core_ln(const float* __restrict__ x,
                                                const float* __restrict__ gamma,
                                                const float* __restrict__ beta,
                                                const float* __restrict__ B,
                                                float acc[2][8][4])
{
    const int K = DIM, N = DIM;
    __shared__ unsigned As[BM][APAD];
    __shared__ unsigned Bs[BK][BPAD];
    const int t = threadIdx.x;
    const int wid = t >> 5, lane = t & 31;
    const int g = lane >> 2, q4 = lane & 3;
    const int wm = wid & 3, wn = wid >> 2;
    const int row0 = blockIdx.y * BM, col0 = blockIdx.x * BN;

    const int arow = t >> 3, acol = (t & 7) * 4;
    const int brow = t >> 5, bcol = (t & 31) * 4;

    const float* Ap = x + (size_t)(row0 + arow) * K + acol;
    const float* Bp = B + (size_t)brow * N + col0 + bcol;

    float rs4[4], murs4[4];
    #pragma unroll
    for (int i = 0; i < 4; i++) {
        float mu = g_mu[row0 + arow + 32 * i];
        float rs = g_rs[row0 + arow + 32 * i];
        rs4[i] = rs;
        murs4[i] = mu * rs;
    }

    float4 la[4], lb[4];
    #pragma unroll
    for (int i = 0; i < 4; i++) la[i] = *(const float4*)(Ap + (size_t)(32 * i) * K);
    #pragma unroll
    for (int i = 0; i < 4; i++) lb[i] = *(const float4*)(Bp + (size_t)(8 * i) * N);

    for (int k0 = 0; k0 < K; k0 += BK) {
        float4 gm = *(const float4*)(gamma + acol + k0);
        float4 bt = *(const float4*)(beta + acol + k0);
        __syncthreads();
        #pragma unroll
        for (int i = 0; i < 4; i++) {
            float nx = fmaf(la[i].x, rs4[i], -murs4[i]);
            float ny = fmaf(la[i].y, rs4[i], -murs4[i]);
            float nz = fmaf(la[i].z, rs4[i], -murs4[i]);
            float nw = fmaf(la[i].w, rs4[i], -murs4[i]);
            uint4 vv;
            vv.x = f2tf(fmaf(nx, gm.x, bt.x));
            vv.y = f2tf(fmaf(ny, gm.y, bt.y));
            vv.z = f2tf(fmaf(nz, gm.z, bt.z));
            vv.w = f2tf(fmaf(nw, gm.w, bt.w));
            *(uint4*)&As[arow + 32 * i][acol] = vv;
        }
        #pragma unroll
        for (int i = 0; i < 4; i++) {
            uint4 vv;
            vv.x = f2tf(lb[i].x); vv.y = f2tf(lb[i].y);
            vv.z = f2tf(lb[i].z); vv.w = f2tf(lb[i].w);
            *(uint4*)&Bs[brow + 8 * i][bcol] = vv;
        }
        __syncthreads();
        if (k0 + BK < K) {
            #pragma unroll
            for (int i = 0; i < 4; i++)
                la[i] = *(const float4*)(Ap + k0 + BK + (size_t)(32 * i) * K);
            #pragma unroll
            for (int i = 0; i < 4; i++)
                lb[i] = *(const float4*)(Bp + (size_t)(k0 + BK + 8 * i) * N);
        }
        #pragma unroll
        for (int kk = 0; kk < 4; kk++) {
            unsigned af[2][4];
            #pragma unroll
            for (int mt = 0; mt < 2; mt++) {
                int r = wm * 32 + mt * 16;
                af[mt][0] = As[r + g][kk * 8 + q4];
                af[mt][1] = As[r + g + 8][kk * 8 + q4];
                af[mt][2] = As[r + g][kk * 8 + q4 + 4];
                af[mt][3] = As[r + g + 8][kk * 8 + q4 + 4];
            }
            #pragma unroll
            for (int nt = 0; nt < 8; nt++) {
                int cb = wn * 64 + nt * 8 + g;
                unsigned b0 = Bs[kk * 8 + q4][cb];
                unsigned b1 = Bs[kk * 8 + q4 + 4][cb];
                mma8(acc[0][nt], af[0], b0, b1);
                mma8(acc[1][nt], af[1], b0, b1);
            }
        }
    }
}

// ---------------- QKV projection (LN fused, Q pre-scaled by SCALE*LOG2E) ----------------
__global__ void __launch_bounds__(256) gemm_qkv(const float* __restrict__ x,
                                                const float* __restrict__ gamma,
                                                const float* __restrict__ beta,
                                                const float* __restrict__ wq,
                                                const float* __restrict__ wk,
                                                const float* __restrict__ wv)
{
    float acc[2][8][4] = {};
    const float* W = (blockIdx.z == 0) ? wq : (blockIdx.z == 1) ? wk : wv;
    gemm_tc_core_ln(x, gamma, beta, W, acc);
    float* dst = (blockIdx.z == 0) ? g_q : (blockIdx.z == 1) ? g_k : g_v;
    float sc = (blockIdx.z == 0) ? (SCALE * LOG2E) : 1.f;

    const int t = threadIdx.x, wid = t >> 5, lane = t & 31;
    const int g = lane >> 2, q4 = lane & 3;
    const int wm = wid & 3, wn = wid >> 2;
    #pragma unroll
    for (int mt = 0; mt < 2; mt++) {
        #pragma unroll
        for (int nt = 0; nt < 8; nt++) {
            int cglob = blockIdx.x * BN + wn * 64 + nt * 8 + q4 * 2;
            int h = cglob >> 6, dh = cglob & 63;
            #pragma unroll
            for (int half = 0; half < 2; half++) {
                int m = blockIdx.y * BM + wm * 32 + mt * 16 + g + half * 8;
                int b = m >> 11, n = m & (SEQ - 1);
                float2 o;
                o.x = __uint_as_float(f2tf(acc[mt][nt][half * 2 + 0] * sc));
                o.y = __uint_as_float(f2tf(acc[mt][nt][half * 2 + 1] * sc));
                *(float2*)(dst + ((size_t)(b * HEADS + h) * SEQ + n) * DH + dh) = o;
            }
        }
    }
}

// ---------------- wcomb = wo @ w_out ----------------
__global__ void __launch_bounds__(256) gemm_wcomb(const float* __restrict__ wo,
                                                  const float* __restrict__ wout)
{
    float acc[2][8][4] = {};
    gemm_tc_core(wo, wout, DIM, DIM, acc);
    const int t = threadIdx.x, wid = t >> 5, lane = t & 31;
    const int g = lane >> 2, q4 = lane & 3;
    const int wm = wid & 3, wn = wid >> 2;
    #pragma unroll
    for (int mt = 0; mt < 2; mt++) {
        #pragma unroll
        for (int nt = 0; nt < 8; nt++) {
            int c = blockIdx.x * BN + wn * 64 + nt * 8 + q4 * 2;
            #pragma unroll
            for (int half = 0; half < 2; half++) {
                int r = blockIdx.y * BM + wm * 32 + mt * 16 + g + half * 8;
                float2 o = make_float2(acc[mt][nt][half * 2 + 0], acc[mt][nt][half * 2 + 1]);
                *(float2*)(g_wcomb + (size_t)r * DIM + c) = o;
            }
        }
    }
}

// ---------------- final projection ----------------
__global__ void __launch_bounds__(256) gemm_out(const float* __restrict__ bias,
                                                float* __restrict__ C)
{
    float acc[2][8][4] = {};
    gemm_tc_core(g_attn, g_wcomb, DIM, DIM, acc);
    const int t = threadIdx.x, wid = t >> 5, lane = t & 31;
    const int g = lane >> 2, q4 = lane & 3;
    const int wm = wid & 3, wn = wid >> 2;
    #pragma unroll
    for (int mt = 0; mt < 2; mt++) {
        #pragma unroll
        for (int nt = 0; nt < 8; nt++) {
            int c = blockIdx.x * BN + wn * 64 + nt * 8 + q4 * 2;
            float2 bb = *(const float2*)(bias + c);
            #pragma unroll
            for (int half = 0; half < 2; half++) {
                int r = blockIdx.y * BM + wm * 32 + mt * 16 + g + half * 8;
                float2 o = make_float2(acc[mt][nt][half * 2 + 0] + bb.x,
                                       acc[mt][nt][half * 2 + 1] + bb.y);
                *(float2*)(C + (size_t)r * DIM + c) = o;
            }
        }
    }
}

// ---------------- tf32 flash attention, 3-stage cp.async ring, 1 sync/tile ----------------
#define KPAD 68
#define VPAD 72
#define KW (64 * KPAD)
#define VW (64 * VPAD)
#define NT (SEQ / 64)                       // 32 kv tiles
#define ATTN_SMEM ((3 * KW + 3 * VW) * 4)   // 107520 bytes

__global__ void __launch_bounds__(256) attn_tc()
{
    extern __shared__ unsigned dsm[];

    const int t = threadIdx.x, wid = t >> 5, lane = t & 31;
    const int g = lane >> 2, q4 = lane & 3;
    const int bh = blockIdx.y;
    const int q0 = blockIdx.x * 128 + wid * 16;

    const float* qb = g_q + (size_t)bh * SEQ * DH;
    const float* kb = g_k + (size_t)bh * SEQ * DH;
    const float* vb = g_v + (size_t)bh * SEQ * DH;

    // loader: thread -> row lr (0..63), col chunk base lc (+16*i)
    const int lr = t >> 2, lc = (t & 3) * 4;
    unsigned kst[3], vst[3];
    kst[0] = (unsigned)__cvta_generic_to_shared(dsm + lr * KPAD + lc);
    kst[1] = kst[0] + KW * 4;
    kst[2] = kst[0] + 2 * KW * 4;
    vst[0] = (unsigned)__cvta_generic_to_shared(dsm + 3 * KW + lr * VPAD + lc);
    vst[1] = vst[0] + VW * 4;
    vst[2] = vst[0] + 2 * VW * 4;
    const float* kgp = kb + (size_t)lr * DH + lc;
    const float* vgp = vb + (size_t)lr * DH + lc;

    // prologue: tiles 0,1 -> buffers 0,1
    #pragma unroll
    for (int i = 0; i < 4; i++) cpa16(kst[0] + i * 64, kgp + 16 * i);
    #pragma unroll
    for (int i = 0; i < 4; i++) cpa16(vst[0] + i * 64, vgp + 16 * i);
    asm volatile("cp.async.commit_group;\n");
    #pragma unroll
    for (int i = 0; i < 4; i++) cpa16(kst[1] + i * 64, kgp + 64 * DH + 16 * i);
    #pragma unroll
    for (int i = 0; i < 4; i++) cpa16(vst[1] + i * 64, vgp + 64 * DH + 16 * i);
    asm volatile("cp.async.commit_group;\n");

    // Q fragments in registers (pre-scaled tf32*LOG2E from qkv epilogue)
    unsigned qf[8][4];
    #pragma unroll
    for (int kk = 0; kk < 8; kk++) {
        qf[kk][0] = __float_as_uint(qb[(size_t)(q0 + g) * DH + kk * 8 + q4]);
        qf[kk][1] = __float_as_uint(qb[(size_t)(q0 + g + 8) * DH + kk * 8 + q4]);
        qf[kk][2] = __float_as_uint(qb[(size_t)(q0 + g) * DH + kk * 8 + q4 + 4]);
        qf[kk][3] = __float_as_uint(qb[(size_t)(q0 + g + 8) * DH + kk * 8 + q4 + 4]);
    }

    float o[8][4];
    #pragma unroll
    for (int nt = 0; nt < 8; nt++)
        #pragma unroll
        for (int j = 0; j < 4; j++) o[nt][j] = 0.f;
    float mA = -1e30f, mB = -1e30f, lA = 0.f, lB = 0.f;

    for (int kt = 0; kt < NT; kt++) {
        // tile kt ready when <=1 newer groups pending (last tile: 0)
        if (kt < NT - 1) asm volatile("cp.async.wait_group 1;\n");
        else             asm volatile("cp.async.wait_group 0;\n");
        __syncthreads();   // publish tile kt; all warps are past compute of kt-1

        // refill the buffer tile kt-1 just vacated with tile kt+2
        if (kt + 2 < NT) {
            int nb = (kt + 2) % 3;
            const float* kn = kgp + (size_t)(kt + 2) * 64 * DH;
            const float* vn = vgp + (size_t)(kt + 2) * 64 * DH;
            #pragma unroll
            for (int i = 0; i < 4; i++) cpa16(kst[nb] + i * 64, kn + 16 * i);
            #pragma unroll
            for (int i = 0; i < 4; i++) cpa16(vst[nb] + i * 64, vn + 16 * i);
            asm volatile("cp.async.commit_group;\n");
        }

        const unsigned* Ks = dsm + (size_t)(kt % 3) * KW;
        const unsigned* Vs = dsm + 3 * KW + (size_t)(kt % 3) * VW;

        // S = Q K^T  (log2-domain logits)
        float s[8][4];
        #pragma unroll
        for (int nt = 0; nt < 8; nt++)
            #pragma unroll
            for (int j = 0; j < 4; j++) s[nt][j] = 0.f;
        #pragma unroll
        for (int kk = 0; kk < 8; kk++) {
            #pragma unroll
            for (int nt = 0; nt < 8; nt++) {
                unsigned b0 = Ks[(nt * 8 + g) * KPAD + kk * 8 + q4];
                unsigned b1 = Ks[(nt * 8 + g) * KPAD + kk * 8 + q4 + 4];
                mma8(s[nt], qf[kk], b0, b1);
            }
        }

        // online softmax (base-2): thread owns rows g (regs 0,1) and g+8 (regs 2,3)
        float mxA = -1e30f, mxB = -1e30f;
        #pragma unroll
        for (int nt = 0; nt < 8; nt++) {
            mxA = fmaxf(mxA, fmaxf(s[nt][0], s[nt][1]));
            mxB = fmaxf(mxB, fmaxf(s[nt][2], s[nt][3]));
        }
        mxA = fmaxf(mxA, __shfl_xor_sync(0xffffffffu, mxA, 1));
        mxA = fmaxf(mxA, __shfl_xor_sync(0xffffffffu, mxA, 2));
        mxB = fmaxf(mxB, __shfl_xor_sync(0xffffffffu, mxB, 1));
        mxB = fmaxf(mxB, __shfl_xor_sync(0xffffffffu, mxB, 2));
        float mnA = fmaxf(mA, mxA), mnB = fmaxf(mB, mxB);
        float cA = exp2f(mA - mnA), cB = exp2f(mB - mnB);
        mA = mnA; mB = mnB;
        float sA = 0.f, sB = 0.f;
        #pragma unroll
        for (int nt = 0; nt < 8; nt++) {
            s[nt][0] = exp2f(s[nt][0] - mnA); sA += s[nt][0];
            s[nt][1] = exp2f(s[nt][1] - mnA); sA += s[nt][1];
            s[nt][2] = exp2f(s[nt][2] - mnB); sB += s[nt][2];
            s[nt][3] = exp2f(s[nt][3] - mnB); sB += s[nt][3];
        }
        sA += __shfl_xor_sync(0xffffffffu, sA, 1);
        sA += __shfl_xor_sync(0xffffffffu, sA, 2);
        sB += __shfl_xor_sync(0xffffffffu, sB, 1);
        sB += __shfl_xor_sync(0xffffffffu, sB, 2);
        lA = lA * cA + sA;
        lB = lB * cB + sB;
        #pragma unroll
        for (int nt = 0; nt < 8; nt++) {
            o[nt][0] *= cA; o[nt][1] *= cA;
            o[nt][2] *= cB; o[nt][3] *= cB;
        }

        // O += P @ V ; P(C-frag) -> A-frag via shuffles
        #pragma unroll
        for (int kk = 0; kk < 8; kk++) {
            int src0 = (lane & 28) | (q4 >> 1);
            int src1 = src0 + 2;
            float v00 = __shfl_sync(0xffffffffu, s[kk][0], src0);
            float v01 = __shfl_sync(0xffffffffu, s[kk][1], src0);
            float v10 = __shfl_sync(0xffffffffu, s[kk][2], src0);
            float v11 = __shfl_sync(0xffffffffu, s[kk][3], src0);
            float w00 = __shfl_sync(0xffffffffu, s[kk][0], src1);
            float w01 = __shfl_sync(0xffffffffu, s[kk][1], src1);
            float w10 = __shfl_sync(0xffffffffu, s[kk][2], src1);
            float w11 = __shfl_sync(0xffffffffu, s[kk][3], src1);
            bool e = (q4 & 1);
            unsigned af[4];
            af[0] = f2tf(e ? v01 : v00);
            af[1] = f2tf(e ? v11 : v10);
            af[2] = f2tf(e ? w01 : w00);
            af[3] = f2tf(e ? w11 : w10);
            #pragma unroll
            for (int nt = 0; nt < 8; nt++) {
                unsigned b0 = Vs[(kk * 8 + q4) * VPAD + nt * 8 + g];
                unsigned b1 = Vs[(kk * 8 + q4 + 4) * VPAD + nt * 8 + g];
                mma8(o[nt], af, b0, b1);
            }
        }
    }

    // normalize + write, re-merging heads
    float iA = 1.f / lA, iB = 1.f / lB;
    int b = bh >> 4, h = bh & 15;
    int nA = blockIdx.x * 128 + wid * 16 + g;
    #pragma unroll
    for (int nt = 0; nt < 8; nt++) {
        int dh = nt * 8 + q4 * 2;
        float2 oa = make_float2(o[nt][0] * iA, o[nt][1] * iA);
        float2 ob = make_float2(o[nt][2] * iB, o[nt][3] * iB);
        *(float2*)(g_attn + ((size_t)b * SEQ + nA) * DIM + h * 64 + dh) = oa;
        *(float2*)(g_attn + ((size_t)b * SEQ + nA + 8) * DIM + h * 64 + dh) = ob;
    }
}

// ---------------- launch ----------------
extern "C" void kernel_launch(void* const* d_in, const int* in_sizes, int n_in,
                              void* d_out, int out_size)
{
    const float* x     = (const float*)d_in[0];
    const float* gamma = (const float*)d_in[1];
    const float* beta  = (const float*)d_in[2];
    const float* wq    = (const float*)d_in[3];
    const float* wk    = (const float*)d_in[4];
    const float* wv    = (const float*)d_in[5];
    const float* wo    = (const float*)d_in[6];
    const float* w_out = (const float*)d_in[7];
    const float* b_out = (const float*)d_in[8];
    float* out = (float*)d_out;

    cudaFuncSetAttribute(attn_tc, cudaFuncAttributeMaxDynamicSharedMemorySize, ATTN_SMEM);

    ln_stats<<<ROWS, 256>>>(x);
    gemm_wcomb<<<dim3(DIM / BN, DIM / BM), 256>>>(wo, w_out);
    gemm_qkv<<<dim3(DIM / BN, ROWS / BM, 3), 256>>>(x, gamma, beta, wq, wk, wv);
    attn_tc<<<dim3(SEQ / 128, NB * HEADS), 256, ATTN_SMEM>>>();
    gemm_out<<<dim3(DIM / BN, ROWS / BM), 256>>>(b_out, out);
}

// round 8
// speedup vs baseline: 1.0031x; 1.0031x over previous
#include <cuda_runtime.h>
#include <cstdint>

#define DIM 1024
#define HEADS 16
#define DH 64
#define SEQ 2048
#define NB 2
#define ROWS (NB * SEQ)        // 4096
#define SCALE 0.125f
#define LOG2E 1.4426950408889634f
#define LNEPS 1e-5f

// ---------------- scratch ----------------
__device__ float g_xn[ROWS * DIM];     // layernorm output
__device__ float g_q[ROWS * DIM];      // tf32 bits, pre-scaled SCALE*LOG2E, dh pair-permuted
__device__ float g_k[ROWS * DIM];      // tf32 bits, dh pair-permuted
__device__ float g_v[ROWS * DIM];      // tf32 bits, natural layout
__device__ float g_attn[ROWS * DIM];   // fp32, heads re-merged [4096,1024]
__device__ float g_wcomb[DIM * DIM];   // wo @ w_out (fp32)

// ---------------- helpers ----------------
__device__ __forceinline__ unsigned f2tf(float x) {
    unsigned u;
    asm("cvt.rna.tf32.f32 %0, %1;" : "=r"(u) : "f"(x));
    return u;
}
__device__ __forceinline__ void mma8(float* c, const unsigned* a, unsigned b0, unsigned b1) {
    asm volatile(
        "mma.sync.aligned.m16n8k8.row.col.f32.tf32.tf32.f32 "
        "{%0,%1,%2,%3}, {%4,%5,%6,%7}, {%8,%9}, {%0,%1,%2,%3};\n"
        : "+f"(c[0]), "+f"(c[1]), "+f"(c[2]), "+f"(c[3])
        : "r"(a[0]), "r"(a[1]), "r"(a[2]), "r"(a[3]), "r"(b0), "r"(b1));
}
__device__ __forceinline__ void cpa16(unsigned dst, const void* src) {
    asm volatile("cp.async.cg.shared.global [%0], [%1], 16;\n" :: "r"(dst), "l"(src));
}

// ---------------- LayerNorm (full output) ----------------
__global__ void __launch_bounds__(256) ln_kernel(const float* __restrict__ x,
                                                 const float* __restrict__ gamma,
                                                 const float* __restrict__ beta)
{
    int row = blockIdx.x;
    int t = threadIdx.x;
    const float4* xr = (const float4*)(x + (size_t)row * DIM);
    float4 v = xr[t];
    float s = v.x + v.y + v.z + v.w;
    float ss = v.x * v.x + v.y * v.y + v.z * v.z + v.w * v.w;
    #pragma unroll
    for (int o = 16; o > 0; o >>= 1) {
        s  += __shfl_xor_sync(0xffffffffu, s, o);
        ss += __shfl_xor_sync(0xffffffffu, ss, o);
    }
    __shared__ float sb[8], ssb[8];
    int w = t >> 5, ln = t & 31;
    if (ln == 0) { sb[w] = s; ssb[w] = ss; }
    __syncthreads();
    float tot = 0.f, tot2 = 0.f;
    #pragma unroll
    for (int i = 0; i < 8; i++) { tot += sb[i]; tot2 += ssb[i]; }
    float mu = tot * (1.f / DIM);
    float var = tot2 * (1.f / DIM) - mu * mu;
    float rs = rsqrtf(var + LNEPS);
    float4 g = ((const float4*)gamma)[t];
    float4 bb = ((const float4*)beta)[t];
    float4 o;
    o.x = (v.x - mu) * rs * g.x + bb.x;
    o.y = (v.y - mu) * rs * g.y + bb.y;
    o.z = (v.z - mu) * rs * g.z + bb.z;
    o.w = (v.w - mu) * rs * g.w + bb.w;
    ((float4*)(g_xn + (size_t)row * DIM))[t] = o;
}

// ---------------- tf32 tensor-core GEMM core ----------------
#define BM 128
#define BN 128
#define BK 32
#define APAD 36     // bank = 4*row + col -> frag loads conflict-free
#define BPAD 136    // bank = 8*row + col -> frag loads conflict-free

__device__ __forceinline__ void gemm_tc_core(const float* __restrict__ A,
                                             const float* __restrict__ B,
                                             int K, int N, float acc[2][8][4])
{
    __shared__ unsigned As[BM][APAD];
    __shared__ unsigned Bs[BK][BPAD];
    const int t = threadIdx.x;
    const int wid = t >> 5, lane = t & 31;
    const int g = lane >> 2, q4 = lane & 3;
    const int wm = wid & 3, wn = wid >> 2;
    const int row0 = blockIdx.y * BM, col0 = blockIdx.x * BN;

    const int arow = t >> 3, acol = (t & 7) * 4;
    const int brow = t >> 5, bcol = (t & 31) * 4;

    const float* Ap = A + (size_t)(row0 + arow) * K + acol;
    const float* Bp = B + (size_t)brow * N + col0 + bcol;

    float4 la[4], lb[4];
    #pragma unroll
    for (int i = 0; i < 4; i++) la[i] = *(const float4*)(Ap + (size_t)(32 * i) * K);
    #pragma unroll
    for (int i = 0; i < 4; i++) lb[i] = *(const float4*)(Bp + (size_t)(8 * i) * N);

    for (int k0 = 0; k0 < K; k0 += BK) {
        __syncthreads();
        #pragma unroll
        for (int i = 0; i < 4; i++) {
            uint4 vv;
            vv.x = f2tf(la[i].x); vv.y = f2tf(la[i].y);
            vv.z = f2tf(la[i].z); vv.w = f2tf(la[i].w);
            *(uint4*)&As[arow + 32 * i][acol] = vv;
        }
        #pragma unroll
        for (int i = 0; i < 4; i++) {
            uint4 vv;
            vv.x = f2tf(lb[i].x); vv.y = f2tf(lb[i].y);
            vv.z = f2tf(lb[i].z); vv.w = f2tf(lb[i].w);
            *(uint4*)&Bs[brow + 8 * i][bcol] = vv;
        }
        __syncthreads();
        if (k0 + BK < K) {
            #pragma unroll
            for (int i = 0; i < 4; i++)
                la[i] = *(const float4*)(Ap + k0 + BK + (size_t)(32 * i) * K);
            #pragma unroll
            for (int i = 0; i < 4; i++)
                lb[i] = *(const float4*)(Bp + (size_t)(k0 + BK + 8 * i) * N);
        }
        #pragma unroll
        for (int kk = 0; kk < 4; kk++) {
            unsigned af[2][4];
            #pragma unroll
            for (int mt = 0; mt < 2; mt++) {
                int r = wm * 32 + mt * 16;
                af[mt][0] = As[r + g][kk * 8 + q4];
                af[mt][1] = As[r + g + 8][kk * 8 + q4];
                af[mt][2] = As[r + g][kk * 8 + q4 + 4];
                af[mt][3] = As[r + g + 8][kk * 8 + q4 + 4];
            }
            #pragma unroll
            for (int nt = 0; nt < 8; nt++) {
                int cb = wn * 64 + nt * 8 + g;
                unsigned b0 = Bs[kk * 8 + q4][cb];
                unsigned b1 = Bs[kk * 8 + q4 + 4][cb];
                mma8(acc[0][nt], af[0], b0, b1);
                mma8(acc[1][nt], af[1], b0, b1);
            }
        }
    }
}

// ---------------- QKV projection ----------------
// q,k: dh pair-permuted within 8-groups (orig r -> pos: r<4 ? 2r : 2r-7); v: natural.
__global__ void __launch_bounds__(256) gemm_qkv(const float* __restrict__ wq,
                                                const float* __restrict__ wk,
                                                const float* __restrict__ wv)
{
    float acc[2][8][4] = {};
    const float* W = (blockIdx.z == 0) ? wq : (blockIdx.z == 1) ? wk : wv;
    gemm_tc_core(g_xn, W, DIM, DIM, acc);
    float* dst = (blockIdx.z == 0) ? g_q : (blockIdx.z == 1) ? g_k : g_v;
    const float sc = (blockIdx.z == 0) ? (SCALE * LOG2E) : 1.f;
    const bool permute = (blockIdx.z != 2);

    const int t = threadIdx.x, wid = t >> 5, lane = t & 31;
    const int g = lane >> 2, q4 = lane & 3;
    const int wm = wid & 3, wn = wid >> 2;
    const int r0 = q4 * 2, r1 = r0 + 1;
    const int p0 = (r0 < 4) ? 2 * r0 : 2 * r0 - 7;
    const int p1 = (r1 < 4) ? 2 * r1 : 2 * r1 - 7;

    #pragma unroll
    for (int mt = 0; mt < 2; mt++) {
        #pragma unroll
        for (int nt = 0; nt < 8; nt++) {
            int cglob = blockIdx.x * BN + wn * 64 + nt * 8 + q4 * 2;
            int h = cglob >> 6;
            int dhb = (cglob & 63) & ~7;     // 8-group base within head
            #pragma unroll
            for (int half = 0; half < 2; half++) {
                int m = blockIdx.y * BM + wm * 32 + mt * 16 + g + half * 8;
                int b = m >> 11, n = m & (SEQ - 1);
                float* rowp = dst + ((size_t)(b * HEADS + h) * SEQ + n) * DH + dhb;
                unsigned u0 = f2tf(acc[mt][nt][half * 2 + 0] * sc);
                unsigned u1 = f2tf(acc[mt][nt][half * 2 + 1] * sc);
                if (permute) {
                    ((unsigned*)rowp)[p0] = u0;
                    ((unsigned*)rowp)[p1] = u1;
                } else {
                    *(uint2*)(rowp + r0) = make_uint2(u0, u1);
                }
            }
        }
    }
}

// ---------------- wcomb = wo @ w_out ----------------
__global__ void __launch_bounds__(256) gemm_wcomb(const float* __restrict__ wo,
                                                  const float* __restrict__ wout)
{
    float acc[2][8][4] = {};
    gemm_tc_core(wo, wout, DIM, DIM, acc);
    const int t = threadIdx.x, wid = t >> 5, lane = t & 31;
    const int g = lane >> 2, q4 = lane & 3;
    const int wm = wid & 3, wn = wid >> 2;
    #pragma unroll
    for (int mt = 0; mt < 2; mt++) {
        #pragma unroll
        for (int nt = 0; nt < 8; nt++) {
            int c = blockIdx.x * BN + wn * 64 + nt * 8 + q4 * 2;
            #pragma unroll
            for (int half = 0; half < 2; half++) {
                int r = blockIdx.y * BM + wm * 32 + mt * 16 + g + half * 8;
                float2 o = make_float2(acc[mt][nt][half * 2 + 0], acc[mt][nt][half * 2 + 1]);
                *(float2*)(g_wcomb + (size_t)r * DIM + c) = o;
            }
        }
    }
}

// ---------------- final projection ----------------
__global__ void __launch_bounds__(256) gemm_out(const float* __restrict__ bias,
                                                float* __restrict__ C)
{
    float acc[2][8][4] = {};
    gemm_tc_core(g_attn, g_wcomb, DIM, DIM, acc);
    const int t = threadIdx.x, wid = t >> 5, lane = t & 31;
    const int g = lane >> 2, q4 = lane & 3;
    const int wm = wid & 3, wn = wid >> 2;
    #pragma unroll
    for (int mt = 0; mt < 2; mt++) {
        #pragma unroll
        for (int nt = 0; nt < 8; nt++) {
            int c = blockIdx.x * BN + wn * 64 + nt * 8 + q4 * 2;
            float2 bb = *(const float2*)(bias + c);
            #pragma unroll
            for (int half = 0; half < 2; half++) {
                int r = blockIdx.y * BM + wm * 32 + mt * 16 + g + half * 8;
                float2 o = make_float2(acc[mt][nt][half * 2 + 0] + bb.x,
                                       acc[mt][nt][half * 2 + 1] + bb.y);
                *(float2*)(C + (size_t)r * DIM + c) = o;
            }
        }
    }
}

// ---------------- tf32 flash attention ----------------
// 2-stage cp.async K/V ring + warp-private P smem (no block barrier for P).
// K: LDS.64 B-frags thanks to global pair-permuted dh. V: natural.
#define KPAD 68
#define VPAD 72
#define PPAD 68
#define KW (64 * KPAD)
#define VW (64 * VPAD)
#define PW (16 * PPAD)
#define NT (SEQ / 64)
#define ATTN_SMEM ((2 * KW + 2 * VW + 8 * PW) * 4)   // 106496 bytes

__global__ void __launch_bounds__(256) attn_tc()
{
    extern __shared__ unsigned dsm[];

    const int t = threadIdx.x, wid = t >> 5, lane = t & 31;
    const int g = lane >> 2, q4 = lane & 3;
    const int bh = blockIdx.y;
    const int q0 = blockIdx.x * 128 + wid * 16;

    const float* qb = g_q + (size_t)bh * SEQ * DH;
    const float* kb = g_k + (size_t)bh * SEQ * DH;
    const float* vb = g_v + (size_t)bh * SEQ * DH;

    // loader mapping
    const int lr = t >> 2, lc = (t & 3) * 4;
    unsigned kst[2], vst[2];
    kst[0] = (unsigned)__cvta_generic_to_shared(dsm + lr * KPAD + lc);
    kst[1] = kst[0] + KW * 4;
    vst[0] = (unsigned)__cvta_generic_to_shared(dsm + 2 * KW + lr * VPAD + lc);
    vst[1] = vst[0] + VW * 4;
    const float* kgp = kb + (size_t)lr * DH + lc;
    const float* vgp = vb + (size_t)lr * DH + lc;

    unsigned* Pw = dsm + 2 * KW + 2 * VW + wid * PW;

    // Q fragments (pair-permuted layout: (orig q4, q4+4) adjacent)
    unsigned qf[8][4];
    {
        const float* qr0 = qb + (size_t)(q0 + g) * DH;
        const float* qr1 = qb + (size_t)(q0 + g + 8) * DH;
        #pragma unroll
        for (int kk = 0; kk < 8; kk++) {
            uint2 a = *(const uint2*)(qr0 + kk * 8 + 2 * q4);
            uint2 b = *(const uint2*)(qr1 + kk * 8 + 2 * q4);
            qf[kk][0] = a.x; qf[kk][2] = a.y;
            qf[kk][1] = b.x; qf[kk][3] = b.y;
        }
    }

    float o[8][4];
    #pragma unroll
    for (int nt = 0; nt < 8; nt++)
        #pragma unroll
        for (int j = 0; j < 4; j++) o[nt][j] = 0.f;
    float mA = -1e30f, mB = -1e30f, lA = 0.f, lB = 0.f;

    // prologue: tile 0 -> buffer 0
    #pragma unroll
    for (int i = 0; i < 4; i++) cpa16(kst[0] + i * 64, kgp + 16 * i);
    #pragma unroll
    for (int i = 0; i < 4; i++) cpa16(vst[0] + i * 64, vgp + 16 * i);
    asm volatile("cp.async.commit_group;\n");

    for (int kt = 0; kt < NT; kt++) {
        const int cur = kt & 1;
        if (kt + 1 < NT) {
            const float* kn = kgp + (size_t)(kt + 1) * 64 * DH;
            const float* vn = vgp + (size_t)(kt + 1) * 64 * DH;
            #pragma unroll
            for (int i = 0; i < 4; i++) cpa16(kst[cur ^ 1] + i * 64, kn + 16 * i);
            #pragma unroll
            for (int i = 0; i < 4; i++) cpa16(vst[cur ^ 1] + i * 64, vn + 16 * i);
            asm volatile("cp.async.commit_group;\n");
            asm volatile("cp.async.wait_group 1;\n");
        } else {
            asm volatile("cp.async.wait_group 0;\n");
        }
        __syncthreads();

        const unsigned* Ks = dsm + (size_t)cur * KW;
        const unsigned* Vs = dsm + 2 * KW + (size_t)cur * VW;

        // S = Q K^T (log2-domain; K pair-permuted -> LDS.64 B-frags)
        float s[8][4];
        #pragma unroll
        for (int nt = 0; nt < 8; nt++)
            #pragma unroll
            for (int j = 0; j < 4; j++) s[nt][j] = 0.f;
        #pragma unroll
        for (int kk = 0; kk < 8; kk++) {
            #pragma unroll
            for (int nt = 0; nt < 8; nt++) {
                uint2 bb = *(const uint2*)&Ks[(nt * 8 + g) * KPAD + kk * 8 + 2 * q4];
                mma8(s[nt], qf[kk], bb.x, bb.y);
            }
        }

        // online softmax (base-2)
        float mxA = -1e30f, mxB = -1e30f;
        #pragma unroll
        for (int nt = 0; nt < 8; nt++) {
            mxA = fmaxf(mxA, fmaxf(s[nt][0], s[nt][1]));
            mxB = fmaxf(mxB, fmaxf(s[nt][2], s[nt][3]));
        }
        mxA = fmaxf(mxA, __shfl_xor_sync(0xffffffffu, mxA, 1));
        mxA = fmaxf(mxA, __shfl_xor_sync(0xffffffffu, mxA, 2));
        mxB = fmaxf(mxB, __shfl_xor_sync(0xffffffffu, mxB, 1));
        mxB = fmaxf(mxB, __shfl_xor_sync(0xffffffffu, mxB, 2));
        float mnA = fmaxf(mA, mxA), mnB = fmaxf(mB, mxB);
        float cA = exp2f(mA - mnA), cB = exp2f(mB - mnB);
        mA = mnA; mB = mnB;
        float sA = 0.f, sB = 0.f;
        #pragma unroll
        for (int nt = 0; nt < 8; nt++) {
            s[nt][0] = exp2f(s[nt][0] - mnA); sA += s[nt][0];
            s[nt][1] = exp2f(s[nt][1] - mnA); sA += s[nt][1];
            s[nt][2] = exp2f(s[nt][2] - mnB); sB += s[nt][2];
            s[nt][3] = exp2f(s[nt][3] - mnB); sB += s[nt][3];
        }
        sA += __shfl_xor_sync(0xffffffffu, sA, 1);
        sA += __shfl_xor_sync(0xffffffffu, sA, 2);
        sB += __shfl_xor_sync(0xffffffffu, sB, 1);
        sB += __shfl_xor_sync(0xffffffffu, sB, 2);
        lA = lA * cA + sA;
        lB = lB * cB + sB;
        #pragma unroll
        for (int nt = 0; nt < 8; nt++) {
            o[nt][0] *= cA; o[nt][1] *= cA;
            o[nt][2] *= cB; o[nt][3] *= cB;
        }

        // P -> warp-private smem (tf32), then A-frags via LDS
        #pragma unroll
        for (int nt = 0; nt < 8; nt++) {
            uint2 lo = make_uint2(f2tf(s[nt][0]), f2tf(s[nt][1]));
            uint2 hi = make_uint2(f2tf(s[nt][2]), f2tf(s[nt][3]));
            *(uint2*)&Pw[g * PPAD + nt * 8 + 2 * q4] = lo;
            *(uint2*)&Pw[(g + 8) * PPAD + nt * 8 + 2 * q4] = hi;
        }
        __syncwarp();

        // O += P @ V
        #pragma unroll
        for (int kk = 0; kk < 8; kk++) {
            unsigned af[4];
            af[0] = Pw[g * PPAD + kk * 8 + q4];
            af[1] = Pw[(g + 8) * PPAD + kk * 8 + q4];
            af[2] = Pw[g * PPAD + kk * 8 + q4 + 4];
            af[3] = Pw[(g + 8) * PPAD + kk * 8 + q4 + 4];
            #pragma unroll
            for (int nt = 0; nt < 8; nt++) {
                unsigned b0 = Vs[(kk * 8 + q4) * VPAD + nt * 8 + g];
                unsigned b1 = Vs[(kk * 8 + q4 + 4) * VPAD + nt * 8 + g];
                mma8(o[nt], af, b0, b1);
            }
        }
        __syncthreads();
    }

    // normalize + write, re-merging heads
    float iA = 1.f / lA, iB = 1.f / lB;
    int b = bh >> 4, h = bh & 15;
    int nA = blockIdx.x * 128 + wid * 16 + g;
    #pragma unroll
    for (int nt = 0; nt < 8; nt++) {
        int dh = nt * 8 + q4 * 2;
        float2 oa = make_float2(o[nt][0] * iA, o[nt][1] * iA);
        float2 ob = make_float2(o[nt][2] * iB, o[nt][3] * iB);
        *(float2*)(g_attn + ((size_t)b * SEQ + nA) * DIM + h * 64 + dh) = oa;
        *(float2*)(g_attn + ((size_t)b * SEQ + nA + 8) * DIM + h * 64 + dh) = ob;
    }
}

// ---------------- launch ----------------
extern "C" void kernel_launch(void* const* d_in, const int* in_sizes, int n_in,
                              void* d_out, int out_size)
{
    const float* x     = (const float*)d_in[0];
    const float* gamma = (const float*)d_in[1];
    const float* beta  = (const float*)d_in[2];
    const float* wq    = (const float*)d_in[3];
    const float* wk    = (const float*)d_in[4];
    const float* wv    = (const float*)d_in[5];
    const float* wo    = (const float*)d_in[6];
    const float* w_out = (const float*)d_in[7];
    const float* b_out = (const float*)d_in[8];
    float* out = (float*)d_out;

    cudaFuncSetAttribute(attn_tc, cudaFuncAttributeMaxDynamicSharedMemorySize, ATTN_SMEM);

    ln_kernel<<<ROWS, 256>>>(x, gamma, beta);
    gemm_wcomb<<<dim3(DIM / BN, DIM / BM), 256>>>(wo, w_out);
    gemm_qkv<<<dim3(DIM / BN, ROWS / BM, 3), 256>>>(wq, wk, wv);
    attn_tc<<<dim3(SEQ / 128, NB * HEADS), 256, ATTN_SMEM>>>();
    gemm_out<<<dim3(DIM / BN, ROWS / BM), 256>>>(b_out, out);
}

// round 12
// speedup vs baseline: 1.2078x; 1.2040x over previous
#include <cuda_runtime.h>
#include <cstdint>

#define DIM 1024
#define HEADS 16
#define DH 64
#define SEQ 2048
#define NB 2
#define ROWS (NB * SEQ)        // 4096
#define SCALE 0.125f
#define LOG2E 1.4426950408889634f
#define LNEPS 1e-5f

// ---------------- scratch ----------------
__device__ float g_xn[ROWS * DIM];     // layernorm output
__device__ float g_q[ROWS * DIM];      // tf32 bits, pre-scaled SCALE*LOG2E, dh pair-permuted
__device__ float g_k[ROWS * DIM];      // tf32 bits, dh pair-permuted; [bh][n][dh']
__device__ float g_v[ROWS * DIM];      // tf32 bits, TRANSPOSED [bh][dh][n'], n pair-permuted
__device__ float g_attn[ROWS * DIM];   // fp32, heads re-merged [4096,1024]
__device__ float g_wcomb[DIM * DIM];   // wo @ w_out (fp32)

// ---------------- helpers ----------------
__device__ __forceinline__ unsigned f2tf(float x) {
    unsigned u;
    asm("cvt.rna.tf32.f32 %0, %1;" : "=r"(u) : "f"(x));
    return u;
}
__device__ __forceinline__ void mma8(float* c, const unsigned* a, unsigned b0, unsigned b1) {
    asm volatile(
        "mma.sync.aligned.m16n8k8.row.col.f32.tf32.tf32.f32 "
        "{%0,%1,%2,%3}, {%4,%5,%6,%7}, {%8,%9}, {%0,%1,%2,%3};\n"
        : "+f"(c[0]), "+f"(c[1]), "+f"(c[2]), "+f"(c[3])
        : "r"(a[0]), "r"(a[1]), "r"(a[2]), "r"(a[3]), "r"(b0), "r"(b1));
}
__device__ __forceinline__ void cpa16(unsigned dst, const void* src) {
    asm volatile("cp.async.cg.shared.global [%0], [%1], 16;\n" :: "r"(dst), "l"(src));
}

// ---------------- LayerNorm ----------------
__global__ void __launch_bounds__(256) ln_kernel(const float* __restrict__ x,
                                                 const float* __restrict__ gamma,
                                                 const float* __restrict__ beta)
{
    int row = blockIdx.x;
    int t = threadIdx.x;
    const float4* xr = (const float4*)(x + (size_t)row * DIM);
    float4 v = xr[t];
    float s = v.x + v.y + v.z + v.w;
    float ss = v.x * v.x + v.y * v.y + v.z * v.z + v.w * v.w;
    #pragma unroll
    for (int o = 16; o > 0; o >>= 1) {
        s  += __shfl_xor_sync(0xffffffffu, s, o);
        ss += __shfl_xor_sync(0xffffffffu, ss, o);
    }
    __shared__ float sb[8], ssb[8];
    int w = t >> 5, ln = t & 31;
    if (ln == 0) { sb[w] = s; ssb[w] = ss; }
    __syncthreads();
    float tot = 0.f, tot2 = 0.f;
    #pragma unroll
    for (int i = 0; i < 8; i++) { tot += sb[i]; tot2 += ssb[i]; }
    float mu = tot * (1.f / DIM);
    float var = tot2 * (1.f / DIM) - mu * mu;
    float rs = rsqrtf(var + LNEPS);
    float4 g = ((const float4*)gamma)[t];
    float4 bb = ((const float4*)beta)[t];
    float4 o;
    o.x = (v.x - mu) * rs * g.x + bb.x;
    o.y = (v.y - mu) * rs * g.y + bb.y;
    o.z = (v.z - mu) * rs * g.z + bb.z;
    o.w = (v.w - mu) * rs * g.w + bb.w;
    ((float4*)(g_xn + (size_t)row * DIM))[t] = o;
}

// ---------------- tf32 tensor-core GEMM core ----------------
#define BM 128
#define BN 128
#define BK 32
#define APAD 36
#define BPAD 136

__device__ __forceinline__ void gemm_tc_core(const float* __restrict__ A,
                                             const float* __restrict__ B,
                                             int K, int N, float acc[2][8][4])
{
    __shared__ unsigned As[BM][APAD];
    __shared__ unsigned Bs[BK][BPAD];
    const int t = threadIdx.x;
    const int wid = t >> 5, lane = t & 31;
    const int g = lane >> 2, q4 = lane & 3;
    const int wm = wid & 3, wn = wid >> 2;
    const int row0 = blockIdx.y * BM, col0 = blockIdx.x * BN;

    const int arow = t >> 3, acol = (t & 7) * 4;
    const int brow = t >> 5, bcol = (t & 31) * 4;

    const float* Ap = A + (size_t)(row0 + arow) * K + acol;
    const float* Bp = B + (size_t)brow * N + col0 + bcol;

    float4 la[4], lb[4];
    #pragma unroll
    for (int i = 0; i < 4; i++) la[i] = *(const float4*)(Ap + (size_t)(32 * i) * K);
    #pragma unroll
    for (int i = 0; i < 4; i++) lb[i] = *(const float4*)(Bp + (size_t)(8 * i) * N);

    for (int k0 = 0; k0 < K; k0 += BK) {
        __syncthreads();
        #pragma unroll
        for (int i = 0; i < 4; i++) {
            uint4 vv;
            vv.x = f2tf(la[i].x); vv.y = f2tf(la[i].y);
            vv.z = f2tf(la[i].z); vv.w = f2tf(la[i].w);
            *(uint4*)&As[arow + 32 * i][acol] = vv;
        }
        #pragma unroll
        for (int i = 0; i < 4; i++) {
            uint4 vv;
            vv.x = f2tf(lb[i].x); vv.y = f2tf(lb[i].y);
            vv.z = f2tf(lb[i].z); vv.w = f2tf(lb[i].w);
            *(uint4*)&Bs[brow + 8 * i][bcol] = vv;
        }
        __syncthreads();
        if (k0 + BK < K) {
            #pragma unroll
            for (int i = 0; i < 4; i++)
                la[i] = *(const float4*)(Ap + k0 + BK + (size_t)(32 * i) * K);
            #pragma unroll
            for (int i = 0; i < 4; i++)
                lb[i] = *(const float4*)(Bp + (size_t)(k0 + BK + 8 * i) * N);
        }
        #pragma unroll
        for (int kk = 0; kk < 4; kk++) {
            unsigned af[2][4];
            #pragma unroll
            for (int mt = 0; mt < 2; mt++) {
                int r = wm * 32 + mt * 16;
                af[mt][0] = As[r + g][kk * 8 + q4];
                af[mt][1] = As[r + g + 8][kk * 8 + q4];
                af[mt][2] = As[r + g][kk * 8 + q4 + 4];
                af[mt][3] = As[r + g + 8][kk * 8 + q4 + 4];
            }
            #pragma unroll
            for (int nt = 0; nt < 8; nt++) {
                int cb = wn * 64 + nt * 8 + g;
                unsigned b0 = Bs[kk * 8 + q4][cb];
                unsigned b1 = Bs[kk * 8 + q4 + 4][cb];
                mma8(acc[0][nt], af[0], b0, b1);
                mma8(acc[1][nt], af[1], b0, b1);
            }
        }
    }
}

// ---------------- QKV projection ----------------
// q,k: dh pair-permuted within 8-groups (r -> r<4 ? 2r : 2r-7), row-major [bh][n][dh'].
// v:   transposed [bh][dh][n'], seq n pair-permuted within 8-groups (same map).
__global__ void __launch_bounds__(256) gemm_qkv(const float* __restrict__ wq,
                                                const float* __restrict__ wk,
                                                const float* __restrict__ wv)
{
    float acc[2][8][4] = {};
    const float* W = (blockIdx.z == 0) ? wq : (blockIdx.z == 1) ? wk : wv;
    gemm_tc_core(g_xn, W, DIM, DIM, acc);
    const float sc = (blockIdx.z == 0) ? (SCALE * LOG2E) : 1.f;

    const int t = threadIdx.x, wid = t >> 5, lane = t & 31;
    const int g = lane >> 2, q4 = lane & 3;
    const int wm = wid & 3, wn = wid >> 2;

    if (blockIdx.z != 2) {
        float* dst = (blockIdx.z == 0) ? g_q : g_k;
        const int r0 = q4 * 2, r1 = r0 + 1;
        const int p0 = (r0 < 4) ? 2 * r0 : 2 * r0 - 7;
        const int p1 = (r1 < 4) ? 2 * r1 : 2 * r1 - 7;
        #pragma unroll
        for (int mt = 0; mt < 2; mt++) {
            #pragma unroll
            for (int nt = 0; nt < 8; nt++) {
                int cglob = blockIdx.x * BN + wn * 64 + nt * 8 + q4 * 2;
                int h = cglob >> 6;
                int dhb = (cglob & 63) & ~7;
                #pragma unroll
                for (int half = 0; half < 2; half++) {
                    int m = blockIdx.y * BM + wm * 32 + mt * 16 + g + half * 8;
                    int b = m >> 11, n = m & (SEQ - 1);
                    float* rowp = dst + ((size_t)(b * HEADS + h) * SEQ + n) * DH + dhb;
                    ((unsigned*)rowp)[p0] = f2tf(acc[mt][nt][half * 2 + 0] * sc);
                    ((unsigned*)rowp)[p1] = f2tf(acc[mt][nt][half * 2 + 1] * sc);
                }
            }
        }
    } else {
        // V transposed + seq-permuted
        #pragma unroll
        for (int mt = 0; mt < 2; mt++) {
            #pragma unroll
            for (int nt = 0; nt < 8; nt++) {
                int cglob = blockIdx.x * BN + wn * 64 + nt * 8 + q4 * 2;
                int h = cglob >> 6;
                int dh0 = cglob & 63;
                #pragma unroll
                for (int half = 0; half < 2; half++) {
                    int m = blockIdx.y * BM + wm * 32 + mt * 16 + g + half * 8;
                    int b = m >> 11, n = m & (SEQ - 1);
                    int r = n & 7;
                    int np = (n & ~7) | ((r < 4) ? 2 * r : 2 * r - 7);
                    float* base = g_v + ((size_t)(b * HEADS + h) * DH + dh0) * SEQ + np;
                    ((unsigned*)base)[0]   = f2tf(acc[mt][nt][half * 2 + 0]);
                    ((unsigned*)(base + SEQ))[0] = f2tf(acc[mt][nt][half * 2 + 1]);
                }
            }
        }
    }
}

// ---------------- wcomb = wo @ w_out ----------------
__global__ void __launch_bounds__(256) gemm_wcomb(const float* __restrict__ wo,
                                                  const float* __restrict__ wout)
{
    float acc[2][8][4] = {};
    gemm_tc_core(wo, wout, DIM, DIM, acc);
    const int t = threadIdx.x, wid = t >> 5, lane = t & 31;
    const int g = lane >> 2, q4 = lane & 3;
    const int wm = wid & 3, wn = wid >> 2;
    #pragma unroll
    for (int mt = 0; mt < 2; mt++) {
        #pragma unroll
        for (int nt = 0; nt < 8; nt++) {
            int c = blockIdx.x * BN + wn * 64 + nt * 8 + q4 * 2;
            #pragma unroll
            for (int half = 0; half < 2; half++) {
                int r = blockIdx.y * BM + wm * 32 + mt * 16 + g + half * 8;
                float2 o = make_float2(acc[mt][nt][half * 2 + 0], acc[mt][nt][half * 2 + 1]);
                *(float2*)(g_wcomb + (size_t)r * DIM + c) = o;
            }
        }
    }
}

// ---------------- final projection ----------------
__global__ void __launch_bounds__(256) gemm_out(const float* __restrict__ bias,
                                                float* __restrict__ C)
{
    float acc[2][8][4] = {};
    gemm_tc_core(g_attn, g_wcomb, DIM, DIM, acc);
    const int t = threadIdx.x, wid = t >> 5, lane = t & 31;
    const int g = lane >> 2, q4 = lane & 3;
    const int wm = wid & 3, wn = wid >> 2;
    #pragma unroll
    for (int mt = 0; mt < 2; mt++) {
        #pragma unroll
        for (int nt = 0; nt < 8; nt++) {
            int c = blockIdx.x * BN + wn * 64 + nt * 8 + q4 * 2;
            float2 bb = *(const float2*)(bias + c);
            #pragma unroll
            for (int half = 0; half < 2; half++) {
                int r = blockIdx.y * BM + wm * 32 + mt * 16 + g + half * 8;
                float2 o = make_float2(acc[mt][nt][half * 2 + 0] + bb.x,
                                       acc[mt][nt][half * 2 + 1] + bb.y);
                *(float2*)(C + (size_t)r * DIM + c) = o;
            }
        }
    }
}

// ---------------- tf32 flash attention: max-free softmax, LDS.64 frags ----------------
// 3-stage cp.async ring, one __syncthreads per tile.
// K smem [kv][dh'] pad 72; V smem TRANSPOSED [dh][kv'] pad 72 -> all frag LDS.64 conflict-free.
#define KPAD 72
#define VPAD 72
#define KW (64 * KPAD)
#define VW (64 * VPAD)
#define NT (SEQ / 64)
#define ATTN_SMEM ((3 * KW + 3 * VW) * 4)   // 110592 bytes

__global__ void __launch_bounds__(256) attn_tc()
{
    extern __shared__ unsigned dsm[];

    const int t = threadIdx.x, wid = t >> 5, lane = t & 31;
    const int g = lane >> 2, q4 = lane & 3;
    const int bh = blockIdx.y;
    const int q0 = blockIdx.x * 128 + wid * 16;

    const float* qb = g_q + (size_t)bh * SEQ * DH;
    const float* kb = g_k + (size_t)bh * SEQ * DH;
    const float* vb = g_v + (size_t)bh * DH * SEQ;   // transposed [dh][n']

    // loader: thread -> row lr (0..63), 4 chunks of 16B at cols lc+16i
    const int lr = t >> 2, lc = (t & 3) * 4;
    unsigned kst[3], vst[3];
    kst[0] = (unsigned)__cvta_generic_to_shared(dsm + lr * KPAD + lc);
    kst[1] = kst[0] + KW * 4;
    kst[2] = kst[0] + 2 * KW * 4;
    vst[0] = (unsigned)__cvta_generic_to_shared(dsm + 3 * KW + lr * VPAD + lc);
    vst[1] = vst[0] + VW * 4;
    vst[2] = vst[0] + 2 * VW * 4;
    const float* kgp = kb + (size_t)lr * DH + lc;    // K: row=kv, advance rows per tile
    const float* vgp = vb + (size_t)lr * SEQ + lc;   // V^T: row=dh, advance cols per tile

    // prologue: tiles 0,1
    #pragma unroll
    for (int i = 0; i < 4; i++) cpa16(kst[0] + i * 64, kgp + 16 * i);
    #pragma unroll
    for (int i = 0; i < 4; i++) cpa16(vst[0] + i * 64, vgp + 16 * i);
    asm volatile("cp.async.commit_group;\n");
    #pragma unroll
    for (int i = 0; i < 4; i++) cpa16(kst[1] + i * 64, kgp + 64 * DH + 16 * i);
    #pragma unroll
    for (int i = 0; i < 4; i++) cpa16(vst[1] + i * 64, vgp + 64 + 16 * i);
    asm volatile("cp.async.commit_group;\n");

    // Q fragments (dh pair-permuted -> uint2 loads)
    unsigned qf[8][4];
    {
        const float* qr0 = qb + (size_t)(q0 + g) * DH;
        const float* qr1 = qb + (size_t)(q0 + g + 8) * DH;
        #pragma unroll
        for (int kk = 0; kk < 8; kk++) {
            uint2 a = *(const uint2*)(qr0 + kk * 8 + 2 * q4);
            uint2 b = *(const uint2*)(qr1 + kk * 8 + 2 * q4);
            qf[kk][0] = a.x; qf[kk][2] = a.y;
            qf[kk][1] = b.x; qf[kk][3] = b.y;
        }
    }

    float o[8][4];
    #pragma unroll
    for (int nt = 0; nt < 8; nt++)
        #pragma unroll
        for (int j = 0; j < 4; j++) o[nt][j] = 0.f;
    float lA = 0.f, lB = 0.f;

    for (int kt = 0; kt < NT; kt++) {
        if (kt < NT - 1) asm volatile("cp.async.wait_group 1;\n");
        else             asm volatile("cp.async.wait_group 0;\n");
        __syncthreads();

        if (kt + 2 < NT) {
            int nb = (kt + 2) % 3;
            const float* kn = kgp + (size_t)(kt + 2) * 64 * DH;
            const float* vn = vgp + (size_t)(kt + 2) * 64;
            #pragma unroll
            for (int i = 0; i < 4; i++) cpa16(kst[nb] + i * 64, kn + 16 * i);
            #pragma unroll
            for (int i = 0; i < 4; i++) cpa16(vst[nb] + i * 64, vn + 16 * i);
            asm volatile("cp.async.commit_group;\n");
        }

        const unsigned* Ks = dsm + (size_t)(kt % 3) * KW;
        const unsigned* Vs = dsm + 3 * KW + (size_t)(kt % 3) * VW;

        // S = Q K^T (log2-domain; LDS.64 B-frags)
        float s[8][4];
        #pragma unroll
        for (int nt = 0; nt < 8; nt++)
            #pragma unroll
            for (int j = 0; j < 4; j++) s[nt][j] = 0.f;
        #pragma unroll
        for (int kk = 0; kk < 8; kk++) {
            #pragma unroll
            for (int nt = 0; nt < 8; nt++) {
                uint2 bb = *(const uint2*)&Ks[(nt * 8 + g) * KPAD + kk * 8 + 2 * q4];
                mma8(s[nt], qf[kk], bb.x, bb.y);
            }
        }

        // max-free softmax: p = exp2(s), tf32-round, accumulate l per-thread
        #pragma unroll
        for (int nt = 0; nt < 8; nt++) {
            #pragma unroll
            for (int j = 0; j < 4; j++)
                s[nt][j] = __uint_as_float(f2tf(exp2f(s[nt][j])));
            lA += s[nt][0] + s[nt][1];
            lB += s[nt][2] + s[nt][3];
        }

        // O += P @ V ; P(C-frag) -> A-frag via shuffles; V^T smem -> LDS.64 B-frags
        #pragma unroll
        for (int kk = 0; kk < 8; kk++) {
            int src0 = (lane & 28) | (q4 >> 1);
            int src1 = src0 + 2;
            float v00 = __shfl_sync(0xffffffffu, s[kk][0], src0);
            float v01 = __shfl_sync(0xffffffffu, s[kk][1], src0);
            float v10 = __shfl_sync(0xffffffffu, s[kk][2], src0);
            float v11 = __shfl_sync(0xffffffffu, s[kk][3], src0);
            float w00 = __shfl_sync(0xffffffffu, s[kk][0], src1);
            float w01 = __shfl_sync(0xffffffffu, s[kk][1], src1);
            float w10 = __shfl_sync(0xffffffffu, s[kk][2], src1);
            float w11 = __shfl_sync(0xffffffffu, s[kk][3], src1);
            bool e = (q4 & 1);
            unsigned af[4];
            af[0] = __float_as_uint(e ? v01 : v00);
            af[1] = __float_as_uint(e ? v11 : v10);
            af[2] = __float_as_uint(e ? w01 : w00);
            af[3] = __float_as_uint(e ? w11 : w10);
            #pragma unroll
            for (int nt = 0; nt < 8; nt++) {
                // b0/b1 = V[kv=kk*8+q4 / +4][dh=nt*8+g] -> adjacent in V^T permuted cols
                uint2 bb = *(const uint2*)&Vs[(nt * 8 + g) * VPAD + kk * 8 + 2 * q4];
                mma8(o[nt], af, bb.x, bb.y);
            }
        }
    }

    // final l reduction (over q4 group) + normalize + write, re-merging heads
    lA += __shfl_xor_sync(0xffffffffu, lA, 1);
    lA += __shfl_xor_sync(0xffffffffu, lA, 2);
    lB += __shfl_xor_sync(0xffffffffu, lB, 1);
    lB += __shfl_xor_sync(0xffffffffu, lB, 2);
    float iA = 1.f / lA, iB = 1.f / lB;
    int b = bh >> 4, h = bh & 15;
    int nA = blockIdx.x * 128 + wid * 16 + g;
    #pragma unroll
    for (int nt = 0; nt < 8; nt++) {
        int dh = nt * 8 + q4 * 2;
        float2 oa = make_float2(o[nt][0] * iA, o[nt][1] * iA);
        float2 ob = make_float2(o[nt][2] * iB, o[nt][3] * iB);
        *(float2*)(g_attn + ((size_t)b * SEQ + nA) * DIM + h * 64 + dh) = oa;
        *(float2*)(g_attn + ((size_t)b * SEQ + nA + 8) * DIM + h * 64 + dh) = ob;
    }
}

// ---------------- launch ----------------
extern "C" void kernel_launch(void* const* d_in, const int* in_sizes, int n_in,
                              void* d_out, int out_size)
{
    const float* x     = (const float*)d_in[0];
    const float* gamma = (const float*)d_in[1];
    const float* beta  = (const float*)d_in[2];
    const float* wq    = (const float*)d_in[3];
    const float* wk    = (const float*)d_in[4];
    const float* wv    = (const float*)d_in[5];
    const float* wo    = (const float*)d_in[6];
    const float* w_out = (const float*)d_in[7];
    const float* b_out = (const float*)d_in[8];
    float* out = (float*)d_out;

    cudaFuncSetAttribute(attn_tc, cudaFuncAttributeMaxDynamicSharedMemorySize, ATTN_SMEM);

    ln_kernel<<<ROWS, 256>>>(x, gamma, beta);
    gemm_wcomb<<<dim3(DIM / BN, DIM / BM), 256>>>(wo, w_out);
    gemm_qkv<<<dim3(DIM / BN, ROWS / BM, 3), 256>>>(wq, wk, wv);
    attn_tc<<<dim3(SEQ / 128, NB * HEADS), 256, ATTN_SMEM>>>();
    gemm_out<<<dim3(DIM / BN, ROWS / BM), 256>>>(b_out, out);
}

// round 13
// speedup vs baseline: 1.2463x; 1.0319x over previous
#include <cuda_runtime.h>
#include <cstdint>

#define DIM 1024
#define HEADS 16
#define DH 64
#define SEQ 2048
#define NB 2
#define ROWS (NB * SEQ)        // 4096
#define SCALE 0.125f
#define LOG2E 1.4426950408889634f
#define LNEPS 1e-5f

// ---------------- scratch ----------------
__device__ float g_xn[ROWS * DIM];     // layernorm output
__device__ float g_q[ROWS * DIM];      // tf32 bits, pre-scaled SCALE*LOG2E, dh pair-permuted
__device__ float g_k[ROWS * DIM];      // tf32 bits, dh pair-permuted; [bh][n][dh']
__device__ float g_v[ROWS * DIM];      // tf32 bits, TRANSPOSED [bh][dh][n], natural order
__device__ float g_attn[ROWS * DIM];   // fp32, heads re-merged [4096,1024]
__device__ float g_wcomb[DIM * DIM];   // wo @ w_out (fp32)

// ---------------- helpers ----------------
__device__ __forceinline__ unsigned f2tf(float x) {
    unsigned u;
    asm("cvt.rna.tf32.f32 %0, %1;" : "=r"(u) : "f"(x));
    return u;
}
__device__ __forceinline__ void mma8(float* c, const unsigned* a, unsigned b0, unsigned b1) {
    asm volatile(
        "mma.sync.aligned.m16n8k8.row.col.f32.tf32.tf32.f32 "
        "{%0,%1,%2,%3}, {%4,%5,%6,%7}, {%8,%9}, {%0,%1,%2,%3};\n"
        : "+f"(c[0]), "+f"(c[1]), "+f"(c[2]), "+f"(c[3])
        : "r"(a[0]), "r"(a[1]), "r"(a[2]), "r"(a[3]), "r"(b0), "r"(b1));
}
// same mma, accumulators as floats + A given as 4 float regs (renamed C-frag)
__device__ __forceinline__ void mma8f(float* c, float a0, float a1, float a2, float a3,
                                      unsigned b0, unsigned b1) {
    asm volatile(
        "mma.sync.aligned.m16n8k8.row.col.f32.tf32.tf32.f32 "
        "{%0,%1,%2,%3}, {%4,%5,%6,%7}, {%8,%9}, {%0,%1,%2,%3};\n"
        : "+f"(c[0]), "+f"(c[1]), "+f"(c[2]), "+f"(c[3])
        : "r"(__float_as_uint(a0)), "r"(__float_as_uint(a1)),
          "r"(__float_as_uint(a2)), "r"(__float_as_uint(a3)),
          "r"(b0), "r"(b1));
}
__device__ __forceinline__ void cpa16(unsigned dst, const void* src) {
    asm volatile("cp.async.cg.shared.global [%0], [%1], 16;\n" :: "r"(dst), "l"(src));
}

// ---------------- LayerNorm ----------------
__global__ void __launch_bounds__(256) ln_kernel(const float* __restrict__ x,
                                                 const float* __restrict__ gamma,
                                                 const float* __restrict__ beta)
{
    int row = blockIdx.x;
    int t = threadIdx.x;
    const float4* xr = (const float4*)(x + (size_t)row * DIM);
    float4 v = xr[t];
    float s = v.x + v.y + v.z + v.w;
    float ss = v.x * v.x + v.y * v.y + v.z * v.z + v.w * v.w;
    #pragma unroll
    for (int o = 16; o > 0; o >>= 1) {
        s  += __shfl_xor_sync(0xffffffffu, s, o);
        ss += __shfl_xor_sync(0xffffffffu, ss, o);
    }
    __shared__ float sb[8], ssb[8];
    int w = t >> 5, ln = t & 31;
    if (ln == 0) { sb[w] = s; ssb[w] = ss; }
    __syncthreads();
    float tot = 0.f, tot2 = 0.f;
    #pragma unroll
    for (int i = 0; i < 8; i++) { tot += sb[i]; tot2 += ssb[i]; }
    float mu = tot * (1.f / DIM);
    float var = tot2 * (1.f / DIM) - mu * mu;
    float rs = rsqrtf(var + LNEPS);
    float4 g = ((const float4*)gamma)[t];
    float4 bb = ((const float4*)beta)[t];
    float4 o;
    o.x = (v.x - mu) * rs * g.x + bb.x;
    o.y = (v.y - mu) * rs * g.y + bb.y;
    o.z = (v.z - mu) * rs * g.z + bb.z;
    o.w = (v.w - mu) * rs * g.w + bb.w;
    ((float4*)(g_xn + (size_t)row * DIM))[t] = o;
}

// ---------------- tf32 tensor-core GEMM core ----------------
#define BM 128
#define BN 128
#define BK 32
#define APAD 36
#define BPAD 136

__device__ __forceinline__ void gemm_tc_core(const float* __restrict__ A,
                                             const float* __restrict__ B,
                                             int K, int N, float acc[2][8][4])
{
    __shared__ unsigned As[BM][APAD];
    __shared__ unsigned Bs[BK][BPAD];
    const int t = threadIdx.x;
    const int wid = t >> 5, lane = t & 31;
    const int g = lane >> 2, q4 = lane & 3;
    const int wm = wid & 3, wn = wid >> 2;
    const int row0 = blockIdx.y * BM, col0 = blockIdx.x * BN;

    const int arow = t >> 3, acol = (t & 7) * 4;
    const int brow = t >> 5, bcol = (t & 31) * 4;

    const float* Ap = A + (size_t)(row0 + arow) * K + acol;
    const float* Bp = B + (size_t)brow * N + col0 + bcol;

    float4 la[4], lb[4];
    #pragma unroll
    for (int i = 0; i < 4; i++) la[i] = *(const float4*)(Ap + (size_t)(32 * i) * K);
    #pragma unroll
    for (int i = 0; i < 4; i++) lb[i] = *(const float4*)(Bp + (size_t)(8 * i) * N);

    for (int k0 = 0; k0 < K; k0 += BK) {
        __syncthreads();
        #pragma unroll
        for (int i = 0; i < 4; i++) {
            uint4 vv;
            vv.x = f2tf(la[i].x); vv.y = f2tf(la[i].y);
            vv.z = f2tf(la[i].z); vv.w = f2tf(la[i].w);
            *(uint4*)&As[arow + 32 * i][acol] = vv;
        }
        #pragma unroll
        for (int i = 0; i < 4; i++) {
            uint4 vv;
            vv.x = f2tf(lb[i].x); vv.y = f2tf(lb[i].y);
            vv.z = f2tf(lb[i].z); vv.w = f2tf(lb[i].w);
            *(uint4*)&Bs[brow + 8 * i][bcol] = vv;
        }
        __syncthreads();
        if (k0 + BK < K) {
            #pragma unroll
            for (int i = 0; i < 4; i++)
                la[i] = *(const float4*)(Ap + k0 + BK + (size_t)(32 * i) * K);
            #pragma unroll
            for (int i = 0; i < 4; i++)
                lb[i] = *(const float4*)(Bp + (size_t)(k0 + BK + 8 * i) * N);
        }
        #pragma unroll
        for (int kk = 0; kk < 4; kk++) {
            unsigned af[2][4];
            #pragma unroll
            for (int mt = 0; mt < 2; mt++) {
                int r = wm * 32 + mt * 16;
                af[mt][0] = As[r + g][kk * 8 + q4];
                af[mt][1] = As[r + g + 8][kk * 8 + q4];
                af[mt][2] = As[r + g][kk * 8 + q4 + 4];
                af[mt][3] = As[r + g + 8][kk * 8 + q4 + 4];
            }
            #pragma unroll
            for (int nt = 0; nt < 8; nt++) {
                int cb = wn * 64 + nt * 8 + g;
                unsigned b0 = Bs[kk * 8 + q4][cb];
                unsigned b1 = Bs[kk * 8 + q4 + 4][cb];
                mma8(acc[0][nt], af[0], b0, b1);
                mma8(acc[1][nt], af[1], b0, b1);
            }
        }
    }
}

// ---------------- QKV projection ----------------
// q,k: dh pair-permuted within 8-groups (r -> r<4 ? 2r : 2r-7), row-major [bh][n][dh'].
// v:   transposed [bh][dh][n], natural order.
__global__ void __launch_bounds__(256) gemm_qkv(const float* __restrict__ wq,
                                                const float* __restrict__ wk,
                                                const float* __restrict__ wv)
{
    float acc[2][8][4] = {};
    const float* W = (blockIdx.z == 0) ? wq : (blockIdx.z == 1) ? wk : wv;
    gemm_tc_core(g_xn, W, DIM, DIM, acc);
    const float sc = (blockIdx.z == 0) ? (SCALE * LOG2E) : 1.f;

    const int t = threadIdx.x, wid = t >> 5, lane = t & 31;
    const int g = lane >> 2, q4 = lane & 3;
    const int wm = wid & 3, wn = wid >> 2;

    if (blockIdx.z != 2) {
        float* dst = (blockIdx.z == 0) ? g_q : g_k;
        const int r0 = q4 * 2, r1 = r0 + 1;
        const int p0 = (r0 < 4) ? 2 * r0 : 2 * r0 - 7;
        const int p1 = (r1 < 4) ? 2 * r1 : 2 * r1 - 7;
        #pragma unroll
        for (int mt = 0; mt < 2; mt++) {
            #pragma unroll
            for (int nt = 0; nt < 8; nt++) {
                int cglob = blockIdx.x * BN + wn * 64 + nt * 8 + q4 * 2;
                int h = cglob >> 6;
                int dhb = (cglob & 63) & ~7;
                #pragma unroll
                for (int half = 0; half < 2; half++) {
                    int m = blockIdx.y * BM + wm * 32 + mt * 16 + g + half * 8;
                    int b = m >> 11, n = m & (SEQ - 1);
                    float* rowp = dst + ((size_t)(b * HEADS + h) * SEQ + n) * DH + dhb;
                    ((unsigned*)rowp)[p0] = f2tf(acc[mt][nt][half * 2 + 0] * sc);
                    ((unsigned*)rowp)[p1] = f2tf(acc[mt][nt][half * 2 + 1] * sc);
                }
            }
        }
    } else {
        // V transposed, natural order
        #pragma unroll
        for (int mt = 0; mt < 2; mt++) {
            #pragma unroll
            for (int nt = 0; nt < 8; nt++) {
                int cglob = blockIdx.x * BN + wn * 64 + nt * 8 + q4 * 2;
                int h = cglob >> 6;
                int dh0 = cglob & 63;
                #pragma unroll
                for (int half = 0; half < 2; half++) {
                    int m = blockIdx.y * BM + wm * 32 + mt * 16 + g + half * 8;
                    int b = m >> 11, n = m & (SEQ - 1);
                    float* base = g_v + ((size_t)(b * HEADS + h) * DH + dh0) * SEQ + n;
                    ((unsigned*)base)[0]         = f2tf(acc[mt][nt][half * 2 + 0]);
                    ((unsigned*)(base + SEQ))[0] = f2tf(acc[mt][nt][half * 2 + 1]);
                }
            }
        }
    }
}

// ---------------- wcomb = wo @ w_out ----------------
__global__ void __launch_bounds__(256) gemm_wcomb(const float* __restrict__ wo,
                                                  const float* __restrict__ wout)
{
    float acc[2][8][4] = {};
    gemm_tc_core(wo, wout, DIM, DIM, acc);
    const int t = threadIdx.x, wid = t >> 5, lane = t & 31;
    const int g = lane >> 2, q4 = lane & 3;
    const int wm = wid & 3, wn = wid >> 2;
    #pragma unroll
    for (int mt = 0; mt < 2; mt++) {
        #pragma unroll
        for (int nt = 0; nt < 8; nt++) {
            int c = blockIdx.x * BN + wn * 64 + nt * 8 + q4 * 2;
            #pragma unroll
            for (int half = 0; half < 2; half++) {
                int r = blockIdx.y * BM + wm * 32 + mt * 16 + g + half * 8;
                float2 o = make_float2(acc[mt][nt][half * 2 + 0], acc[mt][nt][half * 2 + 1]);
                *(float2*)(g_wcomb + (size_t)r * DIM + c) = o;
            }
        }
    }
}

// ---------------- final projection ----------------
__global__ void __launch_bounds__(256) gemm_out(const float* __restrict__ bias,
                                                float* __restrict__ C)
{
    float acc[2][8][4] = {};
    gemm_tc_core(g_attn, g_wcomb, DIM, DIM, acc);
    const int t = threadIdx.x, wid = t >> 5, lane = t & 31;
    const int g = lane >> 2, q4 = lane & 3;
    const int wm = wid & 3, wn = wid >> 2;
    #pragma unroll
    for (int mt = 0; mt < 2; mt++) {
        #pragma unroll
        for (int nt = 0; nt < 8; nt++) {
            int c = blockIdx.x * BN + wn * 64 + nt * 8 + q4 * 2;
            float2 bb = *(const float2*)(bias + c);
            #pragma unroll
            for (int half = 0; half < 2; half++) {
                int r = blockIdx.y * BM + wm * 32 + mt * 16 + g + half * 8;
                float2 o = make_float2(acc[mt][nt][half * 2 + 0] + bb.x,
                                       acc[mt][nt][half * 2 + 1] + bb.y);
                *(float2*)(C + (size_t)r * DIM + c) = o;
            }
        }
    }
}

// ---------------- tf32 flash attention ----------------
// Max-free base-2 softmax; 3-stage cp.async ring; one __syncthreads per tile.
// S C-frag feeds PV A-frag by REGISTER RENAME {s0,s2,s1,s3}: the PV k-enumeration
// uses the paired order (pos j <-> kv 2j | 2j-7), so V B-frags need naturally
// adjacent kv columns {2q4, 2q4+1} of transposed V -> LDS.64, conflict-free.
#define KPAD 72
#define VPAD 72
#define KW (64 * KPAD)
#define VW (64 * VPAD)
#define NT (SEQ / 64)
#define ATTN_SMEM ((3 * KW + 3 * VW) * 4)   // 110592 bytes

__global__ void __launch_bounds__(256) attn_tc()
{
    extern __shared__ unsigned dsm[];

    const int t = threadIdx.x, wid = t >> 5, lane = t & 31;
    const int g = lane >> 2, q4 = lane & 3;
    const int bh = blockIdx.y;
    const int q0 = blockIdx.x * 128 + wid * 16;

    const float* qb = g_q + (size_t)bh * SEQ * DH;
    const float* kb = g_k + (size_t)bh * SEQ * DH;
    const float* vb = g_v + (size_t)bh * DH * SEQ;   // transposed [dh][n]

    const int lr = t >> 2, lc = (t & 3) * 4;
    unsigned kst[3], vst[3];
    kst[0] = (unsigned)__cvta_generic_to_shared(dsm + lr * KPAD + lc);
    kst[1] = kst[0] + KW * 4;
    kst[2] = kst[0] + 2 * KW * 4;
    vst[0] = (unsigned)__cvta_generic_to_shared(dsm + 3 * KW + lr * VPAD + lc);
    vst[1] = vst[0] + VW * 4;
    vst[2] = vst[0] + 2 * VW * 4;
    const float* kgp = kb + (size_t)lr * DH + lc;    // K: row=kv
    const float* vgp = vb + (size_t)lr * SEQ + lc;   // V^T: row=dh

    // prologue: tiles 0,1
    #pragma unroll
    for (int i = 0; i < 4; i++) cpa16(kst[0] + i * 64, kgp + 16 * i);
    #pragma unroll
    for (int i = 0; i < 4; i++) cpa16(vst[0] + i * 64, vgp + 16 * i);
    asm volatile("cp.async.commit_group;\n");
    #pragma unroll
    for (int i = 0; i < 4; i++) cpa16(kst[1] + i * 64, kgp + 64 * DH + 16 * i);
    #pragma unroll
    for (int i = 0; i < 4; i++) cpa16(vst[1] + i * 64, vgp + 64 + 16 * i);
    asm volatile("cp.async.commit_group;\n");

    // Q fragments (dh pair-permuted -> uint2 loads)
    unsigned qf[8][4];
    {
        const float* qr0 = qb + (size_t)(q0 + g) * DH;
        const float* qr1 = qb + (size_t)(q0 + g + 8) * DH;
        #pragma unroll
        for (int kk = 0; kk < 8; kk++) {
            uint2 a = *(const uint2*)(qr0 + kk * 8 + 2 * q4);
            uint2 b = *(const uint2*)(qr1 + kk * 8 + 2 * q4);
            qf[kk][0] = a.x; qf[kk][2] = a.y;
            qf[kk][1] = b.x; qf[kk][3] = b.y;
        }
    }

    float o[8][4];
    #pragma unroll
    for (int nt = 0; nt < 8; nt++)
        #pragma unroll
        for (int j = 0; j < 4; j++) o[nt][j] = 0.f;
    float lA = 0.f, lB = 0.f;

    for (int kt = 0; kt < NT; kt++) {
        if (kt < NT - 1) asm volatile("cp.async.wait_group 1;\n");
        else             asm volatile("cp.async.wait_group 0;\n");
        __syncthreads();

        if (kt + 2 < NT) {
            int nb = (kt + 2) % 3;
            const float* kn = kgp + (size_t)(kt + 2) * 64 * DH;
            const float* vn = vgp + (size_t)(kt + 2) * 64;
            #pragma unroll
            for (int i = 0; i < 4; i++) cpa16(kst[nb] + i * 64, kn + 16 * i);
            #pragma unroll
            for (int i = 0; i < 4; i++) cpa16(vst[nb] + i * 64, vn + 16 * i);
            asm volatile("cp.async.commit_group;\n");
        }

        const unsigned* Ks = dsm + (size_t)(kt % 3) * KW;
        const unsigned* Vs = dsm + 3 * KW + (size_t)(kt % 3) * VW;

        // S = Q K^T (log2-domain; LDS.64 B-frags)
        float s[8][4];
        #pragma unroll
        for (int nt = 0; nt < 8; nt++)
            #pragma unroll
            for (int j = 0; j < 4; j++) s[nt][j] = 0.f;
        #pragma unroll
        for (int kk = 0; kk < 8; kk++) {
            #pragma unroll
            for (int nt = 0; nt < 8; nt++) {
                uint2 bb = *(const uint2*)&Ks[(nt * 8 + g) * KPAD + kk * 8 + 2 * q4];
                mma8(s[nt], qf[kk], bb.x, bb.y);
            }
        }

        // max-free softmax: p = exp2(s), tf32-round, accumulate l per-thread
        #pragma unroll
        for (int nt = 0; nt < 8; nt++) {
            #pragma unroll
            for (int j = 0; j < 4; j++)
                s[nt][j] = __uint_as_float(f2tf(exp2f(s[nt][j])));
            lA += s[nt][0] + s[nt][1];
            lB += s[nt][2] + s[nt][3];
        }

        // O += P @ V : A-frag = renamed C-frag {s0,s2,s1,s3}; V^T LDS.64 B-frags
        #pragma unroll
        for (int kk = 0; kk < 8; kk++) {
            #pragma unroll
            for (int nt = 0; nt < 8; nt++) {
                uint2 bb = *(const uint2*)&Vs[(nt * 8 + g) * VPAD + kk * 8 + 2 * q4];
                mma8f(o[nt], s[kk][0], s[kk][2], s[kk][1], s[kk][3], bb.x, bb.y);
            }
        }
    }

    // final l reduction (over q4 group) + normalize + write, re-merging heads
    lA += __shfl_xor_sync(0xffffffffu, lA, 1);
    lA += __shfl_xor_sync(0xffffffffu, lA, 2);
    lB += __shfl_xor_sync(0xffffffffu, lB, 1);
    lB += __shfl_xor_sync(0xffffffffu, lB, 2);
    float iA = 1.f / lA, iB = 1.f / lB;
    int b = bh >> 4, h = bh & 15;
    int nA = blockIdx.x * 128 + wid * 16 + g;
    #pragma unroll
    for (int nt = 0; nt < 8; nt++) {
        int dh = nt * 8 + q4 * 2;
        float2 oa = make_float2(o[nt][0] * iA, o[nt][1] * iA);
        float2 ob = make_float2(o[nt][2] * iB, o[nt][3] * iB);
        *(float2*)(g_attn + ((size_t)b * SEQ + nA) * DIM + h * 64 + dh) = oa;
        *(float2*)(g_attn + ((size_t)b * SEQ + nA + 8) * DIM + h * 64 + dh) = ob;
    }
}

// ---------------- launch ----------------
extern "C" void kernel_launch(void* const* d_in, const int* in_sizes, int n_in,
                              void* d_out, int out_size)
{
    const float* x     = (const float*)d_in[0];
    const float* gamma = (const float*)d_in[1];
    const float* beta  = (const float*)d_in[2];
    const float* wq    = (const float*)d_in[3];
    const float* wk    = (const float*)d_in[4];
    const float* wv    = (const float*)d_in[5];
    const float* wo    = (const float*)d_in[6];
    const float* w_out = (const float*)d_in[7];
    const float* b_out = (const float*)d_in[8];
    float* out = (float*)d_out;

    cudaFuncSetAttribute(attn_tc, cudaFuncAttributeMaxDynamicSharedMemorySize, ATTN_SMEM);

    ln_kernel<<<ROWS, 256>>>(x, gamma, beta);
    gemm_wcomb<<<dim3(DIM / BN, DIM / BM), 256>>>(wo, w_out);
    gemm_qkv<<<dim3(DIM / BN, ROWS / BM, 3), 256>>>(wq, wk, wv);
    attn_tc<<<dim3(SEQ / 128, NB * HEADS), 256, ATTN_SMEM>>>();
    gemm_out<<<dim3(DIM / BN, ROWS / BM), 256>>>(b_out, out);
}

// round 14
// speedup vs baseline: 1.2912x; 1.0360x over previous
#include <cuda_runtime.h>
#include <cstdint>

#define DIM 1024
#define HEADS 16
#define DH 64
#define SEQ 2048
#define NB 2
#define ROWS (NB * SEQ)        // 4096
#define SCALE 0.125f
#define LOG2E 1.4426950408889634f
#define LNEPS 1e-5f

// ---------------- scratch ----------------
__device__ float g_xn[ROWS * DIM];     // layernorm output, tf32 bits
__device__ float g_q[ROWS * DIM];      // tf32 bits, pre-scaled SCALE*LOG2E, dh pair-permuted
__device__ float g_k[ROWS * DIM];      // tf32 bits, dh pair-permuted; [bh][n][dh']
__device__ float g_v[ROWS * DIM];      // tf32 bits, TRANSPOSED [bh][dh][n]
__device__ float g_attn[ROWS * DIM];   // tf32 bits, heads re-merged [4096,1024]
__device__ float g_wcomb[DIM * DIM];   // wo @ w_out, tf32 bits
// tf32 copies of weights
__device__ float g_cwq[DIM * DIM];
__device__ float g_cwk[DIM * DIM];
__device__ float g_cwv[DIM * DIM];
__device__ float g_cwo[DIM * DIM];
__device__ float g_cwout[DIM * DIM];

// ---------------- helpers ----------------
__device__ __forceinline__ unsigned f2tf(float x) {
    unsigned u;
    asm("cvt.rna.tf32.f32 %0, %1;" : "=r"(u) : "f"(x));
    return u;
}
__device__ __forceinline__ void mma8(float* c, const unsigned* a, unsigned b0, unsigned b1) {
    asm volatile(
        "mma.sync.aligned.m16n8k8.row.col.f32.tf32.tf32.f32 "
        "{%0,%1,%2,%3}, {%4,%5,%6,%7}, {%8,%9}, {%0,%1,%2,%3};\n"
        : "+f"(c[0]), "+f"(c[1]), "+f"(c[2]), "+f"(c[3])
        : "r"(a[0]), "r"(a[1]), "r"(a[2]), "r"(a[3]), "r"(b0), "r"(b1));
}
__device__ __forceinline__ void mma8f(float* c, float a0, float a1, float a2, float a3,
                                      unsigned b0, unsigned b1) {
    asm volatile(
        "mma.sync.aligned.m16n8k8.row.col.f32.tf32.tf32.f32 "
        "{%0,%1,%2,%3}, {%4,%5,%6,%7}, {%8,%9}, {%0,%1,%2,%3};\n"
        : "+f"(c[0]), "+f"(c[1]), "+f"(c[2]), "+f"(c[3])
        : "r"(__float_as_uint(a0)), "r"(__float_as_uint(a1)),
          "r"(__float_as_uint(a2)), "r"(__float_as_uint(a3)),
          "r"(b0), "r"(b1));
}
__device__ __forceinline__ void cpa16(unsigned dst, const void* src) {
    asm volatile("cp.async.cg.shared.global [%0], [%1], 16;\n" :: "r"(dst), "l"(src));
}

// ---------------- weight pre-conversion to tf32 ----------------
__global__ void __launch_bounds__(256) cvt_w(const float* __restrict__ wq,
                                             const float* __restrict__ wk,
                                             const float* __restrict__ wv,
                                             const float* __restrict__ wo,
                                             const float* __restrict__ wout)
{
    const float* src;
    float* dst;
    switch (blockIdx.y) {
        case 0: src = wq;   dst = g_cwq;   break;
        case 1: src = wk;   dst = g_cwk;   break;
        case 2: src = wv;   dst = g_cwv;   break;
        case 3: src = wo;   dst = g_cwo;   break;
        default: src = wout; dst = g_cwout; break;
    }
    int idx = blockIdx.x * 256 + threadIdx.x;   // float4 index
    float4 v = ((const float4*)src)[idx];
    uint4 u = make_uint4(f2tf(v.x), f2tf(v.y), f2tf(v.z), f2tf(v.w));
    ((uint4*)dst)[idx] = u;
}

// ---------------- LayerNorm (writes tf32 bits) ----------------
__global__ void __launch_bounds__(256) ln_kernel(const float* __restrict__ x,
                                                 const float* __restrict__ gamma,
                                                 const float* __restrict__ beta)
{
    int row = blockIdx.x;
    int t = threadIdx.x;
    const float4* xr = (const float4*)(x + (size_t)row * DIM);
    float4 v = xr[t];
    float s = v.x + v.y + v.z + v.w;
    float ss = v.x * v.x + v.y * v.y + v.z * v.z + v.w * v.w;
    #pragma unroll
    for (int o = 16; o > 0; o >>= 1) {
        s  += __shfl_xor_sync(0xffffffffu, s, o);
        ss += __shfl_xor_sync(0xffffffffu, ss, o);
    }
    __shared__ float sb[8], ssb[8];
    int w = t >> 5, ln = t & 31;
    if (ln == 0) { sb[w] = s; ssb[w] = ss; }
    __syncthreads();
    float tot = 0.f, tot2 = 0.f;
    #pragma unroll
    for (int i = 0; i < 8; i++) { tot += sb[i]; tot2 += ssb[i]; }
    float mu = tot * (1.f / DIM);
    float var = tot2 * (1.f / DIM) - mu * mu;
    float rs = rsqrtf(var + LNEPS);
    float4 g = ((const float4*)gamma)[t];
    float4 bb = ((const float4*)beta)[t];
    uint4 o;
    o.x = f2tf((v.x - mu) * rs * g.x + bb.x);
    o.y = f2tf((v.y - mu) * rs * g.y + bb.y);
    o.z = f2tf((v.z - mu) * rs * g.z + bb.z);
    o.w = f2tf((v.w - mu) * rs * g.w + bb.w);
    ((uint4*)(g_xn + (size_t)row * DIM))[t] = o;
}

// ---------------- tf32 GEMM core: 3-stage cp.async, inputs tf32-at-rest ----------------
#define BM 128
#define BN 128
#define BK 32
#define GSTEPS (DIM / BK)       // 32
#define AWRD (BM * 36)          // 4608 words per A stage (pad 36)
#define BWRD (BK * 136)         // 4352 words per B stage (pad 136)
#define GEMM_SMEM (3 * (AWRD + BWRD) * 4)   // 107520 bytes

__device__ __forceinline__ void gemm_issue(unsigned smbase,
                                           const float* __restrict__ A,
                                           const float* __restrict__ B,
                                           int row0, int col0, int stage, int k0)
{
    const int t = threadIdx.x;
    #pragma unroll
    for (int i = 0; i < 4; i++) {
        int id = t + 256 * i;
        int row = id >> 3, c = (id & 7) * 4;
        cpa16(smbase + (stage * AWRD + row * 36 + c) * 4,
              A + (size_t)(row0 + row) * DIM + k0 + c);
    }
    #pragma unroll
    for (int i = 0; i < 4; i++) {
        int id = t + 256 * i;
        int row = id >> 5, c = (id & 31) * 4;
        cpa16(smbase + (3 * AWRD + stage * BWRD + row * 136 + c) * 4,
              B + (size_t)(k0 + row) * DIM + col0 + c);
    }
    asm volatile("cp.async.commit_group;\n");
}

__device__ __forceinline__ void gemm_tc_core(const float* __restrict__ A,
                                             const float* __restrict__ B,
                                             float acc[2][8][4])
{
    extern __shared__ unsigned sm[];
    const int t = threadIdx.x;
    const int wid = t >> 5, lane = t & 31;
    const int g = lane >> 2, q4 = lane & 3;
    const int wm = wid & 3, wn = wid >> 2;
    const int row0 = blockIdx.y * BM, col0 = blockIdx.x * BN;

    unsigned smbase = (unsigned)__cvta_generic_to_shared(sm);

    gemm_issue(smbase, A, B, row0, col0, 0, 0);
    gemm_issue(smbase, A, B, row0, col0, 1, BK);

    for (int s = 0; s < GSTEPS; s++) {
        if (s < GSTEPS - 1) asm volatile("cp.async.wait_group 1;\n");
        else                asm volatile("cp.async.wait_group 0;\n");
        __syncthreads();
        if (s + 2 < GSTEPS)
            gemm_issue(smbase, A, B, row0, col0, (s + 2) % 3, (s + 2) * BK);

        const unsigned* As = sm + (s % 3) * AWRD;
        const unsigned* Bs = sm + 3 * AWRD + (s % 3) * BWRD;

        #pragma unroll
        for (int kk = 0; kk < 4; kk++) {
            unsigned af[2][4];
            #pragma unroll
            for (int mt = 0; mt < 2; mt++) {
                int r = wm * 32 + mt * 16;
                af[mt][0] = As[(r + g) * 36 + kk * 8 + q4];
                af[mt][1] = As[(r + g + 8) * 36 + kk * 8 + q4];
                af[mt][2] = As[(r + g) * 36 + kk * 8 + q4 + 4];
                af[mt][3] = As[(r + g + 8) * 36 + kk * 8 + q4 + 4];
            }
            #pragma unroll
            for (int nt = 0; nt < 8; nt++) {
                int cb = wn * 64 + nt * 8 + g;
                unsigned b0 = Bs[(kk * 8 + q4) * 136 + cb];
                unsigned b1 = Bs[(kk * 8 + q4 + 4) * 136 + cb];
                mma8(acc[0][nt], af[0], b0, b1);
                mma8(acc[1][nt], af[1], b0, b1);
            }
        }
    }
}

// ---------------- QKV projection ----------------
// q,k: dh pair-permuted within 8-groups (r -> r<4 ? 2r : 2r-7), row-major [bh][n][dh'].
// v:   transposed [bh][dh][n], natural order.
__global__ void __launch_bounds__(256) gemm_qkv()
{
    float acc[2][8][4] = {};
    const float* W = (blockIdx.z == 0) ? g_cwq : (blockIdx.z == 1) ? g_cwk : g_cwv;
    gemm_tc_core(g_xn, W, acc);
    const float sc = (blockIdx.z == 0) ? (SCALE * LOG2E) : 1.f;

    const int t = threadIdx.x, wid = t >> 5, lane = t & 31;
    const int g = lane >> 2, q4 = lane & 3;
    const int wm = wid & 3, wn = wid >> 2;

    if (blockIdx.z != 2) {
        float* dst = (blockIdx.z == 0) ? g_q : g_k;
        const int r0 = q4 * 2, r1 = r0 + 1;
        const int p0 = (r0 < 4) ? 2 * r0 : 2 * r0 - 7;
        const int p1 = (r1 < 4) ? 2 * r1 : 2 * r1 - 7;
        #pragma unroll
        for (int mt = 0; mt < 2; mt++) {
            #pragma unroll
            for (int nt = 0; nt < 8; nt++) {
                int cglob = blockIdx.x * BN + wn * 64 + nt * 8 + q4 * 2;
                int h = cglob >> 6;
                int dhb = (cglob & 63) & ~7;
                #pragma unroll
                for (int half = 0; half < 2; half++) {
                    int m = blockIdx.y * BM + wm * 32 + mt * 16 + g + half * 8;
                    int b = m >> 11, n = m & (SEQ - 1);
                    float* rowp = dst + ((size_t)(b * HEADS + h) * SEQ + n) * DH + dhb;
                    ((unsigned*)rowp)[p0] = f2tf(acc[mt][nt][half * 2 + 0] * sc);
                    ((unsigned*)rowp)[p1] = f2tf(acc[mt][nt][half * 2 + 1] * sc);
                }
            }
        }
    } else {
        #pragma unroll
        for (int mt = 0; mt < 2; mt++) {
            #pragma unroll
            for (int nt = 0; nt < 8; nt++) {
                int cglob = blockIdx.x * BN + wn * 64 + nt * 8 + q4 * 2;
                int h = cglob >> 6;
                int dh0 = cglob & 63;
                #pragma unroll
                for (int half = 0; half < 2; half++) {
                    int m = blockIdx.y * BM + wm * 32 + mt * 16 + g + half * 8;
                    int b = m >> 11, n = m & (SEQ - 1);
                    float* base = g_v + ((size_t)(b * HEADS + h) * DH + dh0) * SEQ + n;
                    ((unsigned*)base)[0]         = f2tf(acc[mt][nt][half * 2 + 0]);
                    ((unsigned*)(base + SEQ))[0] = f2tf(acc[mt][nt][half * 2 + 1]);
                }
            }
        }
    }
}

// ---------------- wcomb = wo @ w_out (tf32 out) ----------------
__global__ void __launch_bounds__(256) gemm_wcomb()
{
    float acc[2][8][4] = {};
    gemm_tc_core(g_cwo, g_cwout, acc);
    const int t = threadIdx.x, wid = t >> 5, lane = t & 31;
    const int g = lane >> 2, q4 = lane & 3;
    const int wm = wid & 3, wn = wid >> 2;
    #pragma unroll
    for (int mt = 0; mt < 2; mt++) {
        #pragma unroll
        for (int nt = 0; nt < 8; nt++) {
            int c = blockIdx.x * BN + wn * 64 + nt * 8 + q4 * 2;
            #pragma unroll
            for (int half = 0; half < 2; half++) {
                int r = blockIdx.y * BM + wm * 32 + mt * 16 + g + half * 8;
                uint2 o = make_uint2(f2tf(acc[mt][nt][half * 2 + 0]),
                                     f2tf(acc[mt][nt][half * 2 + 1]));
                *(uint2*)(g_wcomb + (size_t)r * DIM + c) = o;
            }
        }
    }
}

// ---------------- final projection ----------------
__global__ void __launch_bounds__(256) gemm_out(const float* __restrict__ bias,
                                                float* __restrict__ C)
{
    float acc[2][8][4] = {};
    gemm_tc_core(g_attn, g_wcomb, acc);
    const int t = threadIdx.x, wid = t >> 5, lane = t & 31;
    const int g = lane >> 2, q4 = lane & 3;
    const int wm = wid & 3, wn = wid >> 2;
    #pragma unroll
    for (int mt = 0; mt < 2; mt++) {
        #pragma unroll
        for (int nt = 0; nt < 8; nt++) {
            int c = blockIdx.x * BN + wn * 64 + nt * 8 + q4 * 2;
            float2 bb = *(const float2*)(bias + c);
            #pragma unroll
            for (int half = 0; half < 2; half++) {
                int r = blockIdx.y * BM + wm * 32 + mt * 16 + g + half * 8;
                float2 o = make_float2(acc[mt][nt][half * 2 + 0] + bb.x,
                                       acc[mt][nt][half * 2 + 1] + bb.y);
                *(float2*)(C + (size_t)r * DIM + c) = o;
            }
        }
    }
}

// ---------------- tf32 flash attention (R13 winner, tf32 epilogue) ----------------
#define KPAD 72
#define VPAD 72
#define KW (64 * KPAD)
#define VW (64 * VPAD)
#define NT (SEQ / 64)
#define ATTN_SMEM ((3 * KW + 3 * VW) * 4)   // 110592 bytes

__global__ void __launch_bounds__(256) attn_tc()
{
    extern __shared__ unsigned dsm[];

    const int t = threadIdx.x, wid = t >> 5, lane = t & 31;
    const int g = lane >> 2, q4 = lane & 3;
    const int bh = blockIdx.y;
    const int q0 = blockIdx.x * 128 + wid * 16;

    const float* qb = g_q + (size_t)bh * SEQ * DH;
    const float* kb = g_k + (size_t)bh * SEQ * DH;
    const float* vb = g_v + (size_t)bh * DH * SEQ;

    const int lr = t >> 2, lc = (t & 3) * 4;
    unsigned kst[3], vst[3];
    kst[0] = (unsigned)__cvta_generic_to_shared(dsm + lr * KPAD + lc);
    kst[1] = kst[0] + KW * 4;
    kst[2] = kst[0] + 2 * KW * 4;
    vst[0] = (unsigned)__cvta_generic_to_shared(dsm + 3 * KW + lr * VPAD + lc);
    vst[1] = vst[0] + VW * 4;
    vst[2] = vst[0] + 2 * VW * 4;
    const float* kgp = kb + (size_t)lr * DH + lc;
    const float* vgp = vb + (size_t)lr * SEQ + lc;

    #pragma unroll
    for (int i = 0; i < 4; i++) cpa16(kst[0] + i * 64, kgp + 16 * i);
    #pragma unroll
    for (int i = 0; i < 4; i++) cpa16(vst[0] + i * 64, vgp + 16 * i);
    asm volatile("cp.async.commit_group;\n");
    #pragma unroll
    for (int i = 0; i < 4; i++) cpa16(kst[1] + i * 64, kgp + 64 * DH + 16 * i);
    #pragma unroll
    for (int i = 0; i < 4; i++) cpa16(vst[1] + i * 64, vgp + 64 + 16 * i);
    asm volatile("cp.async.commit_group;\n");

    unsigned qf[8][4];
    {
        const float* qr0 = qb + (size_t)(q0 + g) * DH;
        const float* qr1 = qb + (size_t)(q0 + g + 8) * DH;
        #pragma unroll
        for (int kk = 0; kk < 8; kk++) {
            uint2 a = *(const uint2*)(qr0 + kk * 8 + 2 * q4);
            uint2 b = *(const uint2*)(qr1 + kk * 8 + 2 * q4);
            qf[kk][0] = a.x; qf[kk][2] = a.y;
            qf[kk][1] = b.x; qf[kk][3] = b.y;
        }
    }

    float o[8][4];
    #pragma unroll
    for (int nt = 0; nt < 8; nt++)
        #pragma unroll
        for (int j = 0; j < 4; j++) o[nt][j] = 0.f;
    float lA = 0.f, lB = 0.f;

    for (int kt = 0; kt < NT; kt++) {
        if (kt < NT - 1) asm volatile("cp.async.wait_group 1;\n");
        else             asm volatile("cp.async.wait_group 0;\n");
        __syncthreads();

        if (kt + 2 < NT) {
            int nb = (kt + 2) % 3;
            const float* kn = kgp + (size_t)(kt + 2) * 64 * DH;
            const float* vn = vgp + (size_t)(kt + 2) * 64;
            #pragma unroll
            for (int i = 0; i < 4; i++) cpa16(kst[nb] + i * 64, kn + 16 * i);
            #pragma unroll
            for (int i = 0; i < 4; i++) cpa16(vst[nb] + i * 64, vn + 16 * i);
            asm volatile("cp.async.commit_group;\n");
        }

        const unsigned* Ks = dsm + (size_t)(kt % 3) * KW;
        const unsigned* Vs = dsm + 3 * KW + (size_t)(kt % 3) * VW;

        float s[8][4];
        #pragma unroll
        for (int nt = 0; nt < 8; nt++)
            #pragma unroll
            for (int j = 0; j < 4; j++) s[nt][j] = 0.f;
        #pragma unroll
        for (int kk = 0; kk < 8; kk++) {
            #pragma unroll
            for (int nt = 0; nt < 8; nt++) {
                uint2 bb = *(const uint2*)&Ks[(nt * 8 + g) * KPAD + kk * 8 + 2 * q4];
                mma8(s[nt], qf[kk], bb.x, bb.y);
            }
        }

        #pragma unroll
        for (int nt = 0; nt < 8; nt++) {
            #pragma unroll
            for (int j = 0; j < 4; j++)
                s[nt][j] = __uint_as_float(f2tf(exp2f(s[nt][j])));
            lA += s[nt][0] + s[nt][1];
            lB += s[nt][2] + s[nt][3];
        }

        #pragma unroll
        for (int kk = 0; kk < 8; kk++) {
            #pragma unroll
            for (int nt = 0; nt < 8; nt++) {
                uint2 bb = *(const uint2*)&Vs[(nt * 8 + g) * VPAD + kk * 8 + 2 * q4];
                mma8f(o[nt], s[kk][0], s[kk][2], s[kk][1], s[kk][3], bb.x, bb.y);
            }
        }
    }

    lA += __shfl_xor_sync(0xffffffffu, lA, 1);
    lA += __shfl_xor_sync(0xffffffffu, lA, 2);
    lB += __shfl_xor_sync(0xffffffffu, lB, 1);
    lB += __shfl_xor_sync(0xffffffffu, lB, 2);
    float iA = 1.f / lA, iB = 1.f / lB;
    int b = bh >> 4, h = bh & 15;
    int nA = blockIdx.x * 128 + wid * 16 + g;
    #pragma unroll
    for (int nt = 0; nt < 8; nt++) {
        int dh = nt * 8 + q4 * 2;
        uint2 oa = make_uint2(f2tf(o[nt][0] * iA), f2tf(o[nt][1] * iA));
        uint2 ob = make_uint2(f2tf(o[nt][2] * iB), f2tf(o[nt][3] * iB));
        *(uint2*)(g_attn + ((size_t)b * SEQ + nA) * DIM + h * 64 + dh) = oa;
        *(uint2*)(g_attn + ((size_t)b * SEQ + nA + 8) * DIM + h * 64 + dh) = ob;
    }
}

// ---------------- launch ----------------
extern "C" void kernel_launch(void* const* d_in, const int* in_sizes, int n_in,
                              void* d_out, int out_size)
{
    const float* x     = (const float*)d_in[0];
    const float* gamma = (const float*)d_in[1];
    const float* beta  = (const float*)d_in[2];
    const float* wq    = (const float*)d_in[3];
    const float* wk    = (const float*)d_in[4];
    const float* wv    = (const float*)d_in[5];
    const float* wo    = (const float*)d_in[6];
    const float* w_out = (const float*)d_in[7];
    const float* b_out = (const float*)d_in[8];
    float* out = (float*)d_out;

    cudaFuncSetAttribute(attn_tc, cudaFuncAttributeMaxDynamicSharedMemorySize, ATTN_SMEM);
    cudaFuncSetAttribute(gemm_qkv, cudaFuncAttributeMaxDynamicSharedMemorySize, GEMM_SMEM);
    cudaFuncSetAttribute(gemm_wcomb, cudaFuncAttributeMaxDynamicSharedMemorySize, GEMM_SMEM);
    cudaFuncSetAttribute(gemm_out, cudaFuncAttributeMaxDynamicSharedMemorySize, GEMM_SMEM);

    cvt_w<<<dim3(DIM * DIM / 4 / 256, 5), 256>>>(wq, wk, wv, wo, w_out);
    ln_kernel<<<ROWS, 256>>>(x, gamma, beta);
    gemm_wcomb<<<dim3(DIM / BN, DIM / BM), 256, GEMM_SMEM>>>();
    gemm_qkv<<<dim3(DIM / BN, ROWS / BM, 3), 256, GEMM_SMEM>>>();
    attn_tc<<<dim3(SEQ / 128, NB * HEADS), 256, ATTN_SMEM>>>();
    gemm_out<<<dim3(DIM / BN, ROWS / BM), 256, GEMM_SMEM>>>(b_out, out);
}